// round 1
// baseline (speedup 1.0000x reference)
#include <cuda_runtime.h>
#include <cuda_bf16.h>
#include <math.h>

// Problem shape (fixed by the reference):
//   B=4, T_Q=2048, T_KV=2048, D=1024
// Pipeline (restructured: o = A @ (l @ ov), associativity removes the
// [B,2048,2048] intermediate and halves batched-GEMM FLOPs):
//   G1: emb0 = latent @ Wl^T + bl          [8192,1024]
//   G2: s1   = emb0  @ Wu^T + bu  -> row softmax -> Lrow [B,Tq,1024]
//   G3: Dm   = input @ WA^T + bA           [8192,1024]
//   G4: S2   = Dm    @ WV^T + bV  -> col softmax (over T_kv) -> A
//   G5: ov   = latent @ Wo^T + bo          [8192,1024]
//   G6: Mm   = Lrow^T @ ov   (per batch, TN, 1024x1024, K=2048)
//   G7: o    = A @ Mm        (per batch, NN, 2048x1024, K=1024) -> d_out

#define BD_MODEL 1024
#define BT 2048
#define NB 4
#define MTOT (NB * BT)              // 8192

// ---------------- scratch (no allocation allowed) ----------------
__device__ float g_buf1[MTOT * BD_MODEL];   // emb0 -> Dm -> ov (reused)
__device__ float g_bufL[MTOT * BD_MODEL];   // s1 -> Lrow (softmaxed in place)
__device__ float g_bufA[MTOT * BD_MODEL];   // S2 -> A (softmaxed in place)
__device__ float g_bufM[NB * BD_MODEL * BD_MODEL]; // Mm = l @ ov

// ---------------- generic strided SGEMM ----------------
// C[m,n] = sum_k A[m*asm+k*ask] * B[k*bsk+n*bsn] (+ bias[n])
// BM=BN=128, BK=8, 256 threads, 8x8 per-thread microtile.
// Requires M%128==0, N%128==0, K%8==0 (true for all 7 GEMMs here).
#define BM 128
#define BN 128
#define BK 8

__global__ __launch_bounds__(256, 2)
void sgemm_kernel(const float* __restrict__ A, const float* __restrict__ B,
                  const float* __restrict__ bias, float* __restrict__ C,
                  int M, int N, int K,
                  long long as_m, long long as_k,
                  long long bs_k, long long bs_n,
                  long long abatch, long long bbatch, long long cbatch)
{
    A += (long long)blockIdx.z * abatch;
    B += (long long)blockIdx.z * bbatch;
    C += (long long)blockIdx.z * cbatch;

    const int bm = blockIdx.y * BM;
    const int bn = blockIdx.x * BN;

    __shared__ float As[BK][BM + 4];
    __shared__ float Bs[BK][BN + 4];

    const int t  = threadIdx.x;
    const int ty = t >> 4;          // 0..15
    const int tx = t & 15;          // 0..15

    float acc[8][8];
#pragma unroll
    for (int i = 0; i < 8; i++)
#pragma unroll
        for (int j = 0; j < 8; j++) acc[i][j] = 0.f;

    const bool a_kfast = (as_k == 1);
    const bool b_kfast = (bs_k == 1);

    for (int k0 = 0; k0 < K; k0 += BK) {
        // ---- load A tile (1024 elems / 256 thr = 4 each) ----
        if (a_kfast) {
#pragma unroll
            for (int j = 0; j < 4; j++) {
                int idx = t + 256 * j;
                int kk = idx & 7, mm = idx >> 3;
                As[kk][mm] = A[(long long)(bm + mm) * as_m + (long long)(k0 + kk)];
            }
        } else {
#pragma unroll
            for (int j = 0; j < 4; j++) {
                int idx = t + 256 * j;
                int mm = idx & 127, kk = idx >> 7;
                As[kk][mm] = A[(long long)(bm + mm) * as_m + (long long)(k0 + kk) * as_k];
            }
        }
        // ---- load B tile ----
        if (b_kfast) {
#pragma unroll
            for (int j = 0; j < 4; j++) {
                int idx = t + 256 * j;
                int kk = idx & 7, nn = idx >> 3;
                Bs[kk][nn] = B[(long long)(bn + nn) * bs_n + (long long)(k0 + kk)];
            }
        } else {
#pragma unroll
            for (int j = 0; j < 4; j++) {
                int idx = t + 256 * j;
                int nn = idx & 127, kk = idx >> 7;
                Bs[kk][nn] = B[(long long)(k0 + kk) * bs_k + (long long)(bn + nn) * bs_n];
            }
        }
        __syncthreads();

#pragma unroll
        for (int kk = 0; kk < BK; kk++) {
            float a[8], b[8];
#pragma unroll
            for (int i = 0; i < 8; i++) a[i] = As[kk][ty * 8 + i];
#pragma unroll
            for (int j = 0; j < 8; j++) b[j] = Bs[kk][tx * 8 + j];
#pragma unroll
            for (int i = 0; i < 8; i++)
#pragma unroll
                for (int j = 0; j < 8; j++) acc[i][j] = fmaf(a[i], b[j], acc[i][j]);
        }
        __syncthreads();
    }

    // ---- epilogue ----
#pragma unroll
    for (int i = 0; i < 8; i++) {
        const long long m = bm + ty * 8 + i;
#pragma unroll
        for (int j = 0; j < 8; j++) {
            const int n = bn + tx * 8 + j;
            float v = acc[i][j];
            if (bias) v += bias[n];
            C[m * (long long)N + n] = v;
        }
    }
}

// ---------------- row softmax over 1024 columns, in place ----------------
__global__ __launch_bounds__(256)
void softmax_rows_1024(float* __restrict__ X)
{
    float* p = X + (long long)blockIdx.x * 1024;
    const int t = threadIdx.x;
    __shared__ float red[256];

    float v[4];
#pragma unroll
    for (int j = 0; j < 4; j++) v[j] = p[t + 256 * j];

    float mx = fmaxf(fmaxf(v[0], v[1]), fmaxf(v[2], v[3]));
    red[t] = mx; __syncthreads();
    for (int s = 128; s > 0; s >>= 1) {
        if (t < s) red[t] = fmaxf(red[t], red[t + s]);
        __syncthreads();
    }
    mx = red[0]; __syncthreads();

    float s = 0.f;
#pragma unroll
    for (int j = 0; j < 4; j++) { v[j] = __expf(v[j] - mx); s += v[j]; }
    red[t] = s; __syncthreads();
    for (int s2 = 128; s2 > 0; s2 >>= 1) {
        if (t < s2) red[t] += red[t + s2];
        __syncthreads();
    }
    const float inv = 1.f / red[0];
#pragma unroll
    for (int j = 0; j < 4; j++) p[t + 256 * j] = v[j] * inv;
}

// ---------------- column softmax over T_kv (rows=2048), in place ----------------
// One thread per (batch, column). grid = B*1024/256 blocks.
__global__ __launch_bounds__(256)
void softmax_cols_kernel(float* __restrict__ X, int rows, int cols)
{
    const int g = blockIdx.x * 256 + threadIdx.x;
    const int b = g / cols;
    const int c = g - b * cols;
    float* p = X + (long long)b * rows * cols + c;

    // online max+sum pass
    float mx = -INFINITY, s = 0.f;
    for (int k = 0; k < rows; k++) {
        float x = p[(long long)k * cols];
        if (x > mx) { s = s * __expf(mx - x) + 1.f; mx = x; }
        else        { s += __expf(x - mx); }
    }
    const float inv = 1.f / s;
    for (int k = 0; k < rows; k++) {
        const long long off = (long long)k * cols;
        p[off] = __expf(p[off] - mx) * inv;
    }
}

// ---------------- host launcher ----------------
extern "C" void kernel_launch(void* const* d_in, const int* in_sizes, int n_in,
                              void* d_out, int out_size)
{
    const float* latent = (const float*)d_in[0];   // [B,Tq,D]
    const float* input  = (const float*)d_in[1];   // [B,Tkv,D]
    const float* Wl = (const float*)d_in[2];
    const float* bl = (const float*)d_in[3];
    const float* Wu = (const float*)d_in[4];
    const float* bu = (const float*)d_in[5];
    const float* WA = (const float*)d_in[6];
    const float* bA = (const float*)d_in[7];
    const float* WV = (const float*)d_in[8];
    const float* bV = (const float*)d_in[9];
    const float* Wo = (const float*)d_in[10];
    const float* bo = (const float*)d_in[11];
    float* out = (float*)d_out;

    float *buf1, *bufL, *bufA, *bufM;
    cudaGetSymbolAddress((void**)&buf1, g_buf1);
    cudaGetSymbolAddress((void**)&bufL, g_bufL);
    cudaGetSymbolAddress((void**)&bufA, g_bufA);
    cudaGetSymbolAddress((void**)&bufM, g_bufM);

    const int D = BD_MODEL;
    const long long DK = D;                 // 1024
    dim3 thr(256);

    // Projections: A row-major [M,K] (as_m=K, as_k=1); W [N,K] (bs_k=1, bs_n=K)
    dim3 gProj(D / BN, MTOT / BM, 1);       // (8, 64)

    // G1: emb0 = latent @ Wl^T + bl  -> buf1
    sgemm_kernel<<<gProj, thr>>>(latent, Wl, bl, buf1, MTOT, D, D,
                                 DK, 1, 1, DK, 0, 0, 0);
    // G2: s1 = emb0 @ Wu^T + bu -> bufL ; then row softmax
    sgemm_kernel<<<gProj, thr>>>(buf1, Wu, bu, bufL, MTOT, D, D,
                                 DK, 1, 1, DK, 0, 0, 0);
    softmax_rows_1024<<<MTOT, 256>>>(bufL);

    // G3: Dm = input @ WA^T + bA -> buf1 (emb0 dead)
    sgemm_kernel<<<gProj, thr>>>(input, WA, bA, buf1, MTOT, D, D,
                                 DK, 1, 1, DK, 0, 0, 0);
    // G4: S2 = Dm @ WV^T + bV -> bufA ; then column softmax over T_kv
    sgemm_kernel<<<gProj, thr>>>(buf1, WV, bV, bufA, MTOT, D, D,
                                 DK, 1, 1, DK, 0, 0, 0);
    softmax_cols_kernel<<<(NB * D) / 256, 256>>>(bufA, BT, D);

    // G5: ov = latent @ Wo^T + bo -> buf1 (Dm dead)
    sgemm_kernel<<<gProj, thr>>>(latent, Wo, bo, buf1, MTOT, D, D,
                                 DK, 1, 1, DK, 0, 0, 0);

    // G6: Mm[b] = Lrow[b]^T @ ov[b]   (M=1024, N=1024, K=2048)
    //   A(m,k) = Lrow[k*1024+m]: as_m=1, as_k=1024
    //   B(k,n) = ov[k*1024+n]:   bs_k=1024, bs_n=1
    dim3 g6(D / BN, D / BM, NB);
    sgemm_kernel<<<g6, thr>>>(bufL, buf1, nullptr, bufM, D, D, BT,
                              1, DK, DK, 1,
                              (long long)BT * D, (long long)BT * D,
                              (long long)D * D);

    // G7: o[b] = A[b] @ Mm[b]   (M=2048, N=1024, K=1024) -> d_out
    dim3 g7(D / BN, BT / BM, NB);
    sgemm_kernel<<<g7, thr>>>(bufA, bufM, nullptr, out, BT, D, D,
                              DK, 1, DK, 1,
                              (long long)BT * D, (long long)D * D,
                              (long long)BT * D);
}

// round 3
// speedup vs baseline: 4.3998x; 4.3998x over previous
#include <cuda_runtime.h>
#include <cuda_bf16.h>
#include <cstdint>
#include <math.h>

// ITAttention on GB300, sm_103 *baseline* ISA (no tcgen05 in this toolchain —
// ptxas target is sm_103 without the 'a' suffix). Tensor cores via legacy
// mma.sync.m16n8k16 bf16 HMMA, with bf16 hi/lo 3-product split for fp32-like
// accuracy (~1e-5), on the associativity-restructured pipeline:
//   o = A_sm @ (L^T @ ov)

#define D_MODEL 1024
#define T_SEQ   2048
#define NB      4
#define MTOT    (NB * T_SEQ)       // 8192

// ---------------- scratch (no allocation allowed) ----------------
__device__ __align__(256) __nv_bfloat16 g_lat_hi[MTOT * D_MODEL];
__device__ __align__(256) __nv_bfloat16 g_lat_lo[MTOT * D_MODEL];
__device__ __align__(256) __nv_bfloat16 g_in_hi [MTOT * D_MODEL];
__device__ __align__(256) __nv_bfloat16 g_in_lo [MTOT * D_MODEL];
__device__ __align__(256) __nv_bfloat16 g_w_hi  [5 * D_MODEL * D_MODEL];
__device__ __align__(256) __nv_bfloat16 g_w_lo  [5 * D_MODEL * D_MODEL];
__device__ __align__(256) __nv_bfloat16 g_p1_hi [MTOT * D_MODEL];   // emb0 -> Dm
__device__ __align__(256) __nv_bfloat16 g_p1_lo [MTOT * D_MODEL];
__device__ __align__(256) __nv_bfloat16 g_lt_hi [MTOT * D_MODEL];   // L^T  [B,1024,2048]
__device__ __align__(256) __nv_bfloat16 g_lt_lo [MTOT * D_MODEL];
__device__ __align__(256) __nv_bfloat16 g_ov_hi [MTOT * D_MODEL];   // ov^T [B,1024,2048]
__device__ __align__(256) __nv_bfloat16 g_ov_lo [MTOT * D_MODEL];
__device__ __align__(256) __nv_bfloat16 g_mm_hi [NB * D_MODEL * D_MODEL]; // M^T
__device__ __align__(256) __nv_bfloat16 g_mm_lo [NB * D_MODEL * D_MODEL];
__device__ __align__(256) __nv_bfloat16 g_pa_hi [MTOT * D_MODEL];   // softmaxed A
__device__ __align__(256) __nv_bfloat16 g_pa_lo [MTOT * D_MODEL];
__device__ __align__(256) float         g_f1   [MTOT * D_MODEL];    // s1 / S2 / ov fp32

// ---------------- helpers ----------------
__device__ __forceinline__ uint32_t smem_u32(const void* p) {
    uint32_t a;
    asm("{ .reg .u64 t; cvta.to.shared.u64 t, %1; cvt.u32.u64 %0, t; }" : "=r"(a) : "l"(p));
    return a;
}
__device__ __forceinline__ void cp16(uint32_t dst, const void* src) {
    asm volatile("cp.async.cg.shared.global [%0], [%1], 16;" :: "r"(dst), "l"(src) : "memory");
}
__device__ __forceinline__ void cp_commit() {
    asm volatile("cp.async.commit_group;" ::: "memory");
}

#define LDSM4(r, addr)                                                            \
    asm volatile("ldmatrix.sync.aligned.m8n8.x4.shared.b16 {%0,%1,%2,%3}, [%4];"  \
                 : "=r"((r)[0]), "=r"((r)[1]), "=r"((r)[2]), "=r"((r)[3])         \
                 : "r"(addr))

#define MMA_BF16(d, a, b)                                                          \
    asm volatile("mma.sync.aligned.m16n8k16.row.col.f32.bf16.bf16.f32 "            \
                 "{%0,%1,%2,%3}, {%4,%5,%6,%7}, {%8,%9}, {%0,%1,%2,%3};"           \
                 : "+f"((d)[0]), "+f"((d)[1]), "+f"((d)[2]), "+f"((d)[3])          \
                 : "r"((a)[0]), "r"((a)[1]), "r"((a)[2]), "r"((a)[3]),             \
                   "r"((b)[0]), "r"((b)[1]))

__device__ __forceinline__ void split2(float v0, float v1,
                                       __nv_bfloat16* hi, __nv_bfloat16* lo,
                                       long long off) {
    __nv_bfloat16 h0 = __float2bfloat16(v0);
    __nv_bfloat16 h1 = __float2bfloat16(v1);
    __nv_bfloat16 l0 = __float2bfloat16(v0 - __bfloat162float(h0));
    __nv_bfloat16 l1 = __float2bfloat16(v1 - __bfloat162float(h1));
    *(__nv_bfloat162*)(hi + off) = __halves2bfloat162(h0, h1);
    *(__nv_bfloat162*)(lo + off) = __halves2bfloat162(l0, l1);
}

// ---------------- bf16x3 GEMM: C[M,N] = A @ B^T ----------------
// A pair [M,K] bf16, B pair [N,K] bf16, K-contiguous. BM=128, BN=256, BK=64.
// 256 threads = 8 warps, 2x4 warp grid, warp tile 64x64.
// smem per stage: Ahi 16K | Alo 16K | Bhi 32K | Blo 32K = 96KB; 2 stages = 192KB.
#define STG_BYTES 98304u
#define SMEM_BYTES (2 * 98304)

#define LOAD_STAGE(sidx) do {                                                        \
    const uint32_t base_ = sb + (uint32_t)((sidx) & 1) * STG_BYTES;                  \
    const int k0_ = (sidx) * 64;                                                     \
    _Pragma("unroll")                                                                \
    for (int t_ = 0; t_ < 4; t_++) {                                                 \
        int idx_ = tid + 256 * t_;                                                   \
        int r_ = idx_ >> 3, c_ = idx_ & 7;                                           \
        uint32_t sm_ = base_ + (uint32_t)r_ * 128u +                                 \
                       ((uint32_t)(c_ * 16) ^ ((uint32_t)(r_ & 7) * 16u));           \
        size_t go_ = (size_t)r_ * K + k0_ + c_ * 8;                                  \
        cp16(sm_, Ahi + go_);                                                        \
        cp16(sm_ + 16384u, Alo + go_);                                               \
    }                                                                                \
    _Pragma("unroll")                                                                \
    for (int t_ = 0; t_ < 8; t_++) {                                                 \
        int idx_ = tid + 256 * t_;                                                   \
        int r_ = idx_ >> 3, c_ = idx_ & 7;                                           \
        uint32_t sm_ = base_ + 32768u + (uint32_t)r_ * 128u +                        \
                       ((uint32_t)(c_ * 16) ^ ((uint32_t)(r_ & 7) * 16u));           \
        size_t go_ = (size_t)r_ * K + k0_ + c_ * 8;                                  \
        cp16(sm_, Bhi + go_);                                                        \
        cp16(sm_ + 32768u, Blo + go_);                                               \
    }                                                                                \
    cp_commit();                                                                     \
} while (0)

__global__ void __launch_bounds__(256, 1)
gemm_bf16x3(const __nv_bfloat16* __restrict__ Ahi, const __nv_bfloat16* __restrict__ Alo,
            const __nv_bfloat16* __restrict__ Bhi, const __nv_bfloat16* __restrict__ Blo,
            const float* __restrict__ bias,
            float* __restrict__ Cf,
            __nv_bfloat16* __restrict__ Chi, __nv_bfloat16* __restrict__ Clo,
            int N, int K,
            long long aB, long long bB, long long cB)
{
    extern __shared__ char smem[];
    const uint32_t sb = smem_u32(smem);
    const int tid = threadIdx.x, lane = tid & 31, wid = tid >> 5;
    const int wm = wid >> 2;            // 0..1 -> rows wm*64
    const int wn = wid & 3;             // 0..3 -> cols wn*64
    const long long z = blockIdx.z;
    const int bm = blockIdx.y * 128, bn = blockIdx.x * 256;

    Ahi += z * aB + (long long)bm * K;
    Alo += z * aB + (long long)bm * K;
    Bhi += z * bB + (long long)bn * K;
    Blo += z * bB + (long long)bn * K;

    const int nst = K >> 6;

    LOAD_STAGE(0);
    LOAD_STAGE(1);

    // fragment addressing (offsets relative to stage base)
    const uint32_t swz = ((uint32_t)(lane & 7)) << 4;
    const uint32_t acsel = (uint32_t)(lane >> 4);
    uint32_t aoff[4];
#pragma unroll
    for (int i = 0; i < 4; i++)
        aoff[i] = (uint32_t)(wm * 64 + i * 16 + (lane & 15)) * 128u;
    const uint32_t bcsel = (uint32_t)((lane >> 3) & 1);
    const int brow = (lane & 7) + ((lane >> 4) << 3);
    uint32_t boff[4];
#pragma unroll
    for (int jj = 0; jj < 4; jj++)
        boff[jj] = 32768u + (uint32_t)(wn * 64 + jj * 16 + brow) * 128u;

    float acc[4][8][4];
#pragma unroll
    for (int i = 0; i < 4; i++)
#pragma unroll
        for (int j = 0; j < 8; j++)
#pragma unroll
            for (int r = 0; r < 4; r++) acc[i][j][r] = 0.f;

    for (int s = 0; s < nst; s++) {
        if (s + 1 < nst) asm volatile("cp.async.wait_group 1;" ::: "memory");
        else             asm volatile("cp.async.wait_group 0;" ::: "memory");
        __syncthreads();
        const uint32_t st = sb + (uint32_t)(s & 1) * STG_BYTES;

#pragma unroll
        for (int ks = 0; ks < 4; ks++) {
            uint32_t ahi[4][4], alo[4][4];
            const uint32_t ak = (((uint32_t)(2 * ks) + acsel) << 4) ^ swz;
#pragma unroll
            for (int i = 0; i < 4; i++) {
                const uint32_t ad = st + aoff[i] + ak;
                LDSM4(ahi[i], ad);
                LDSM4(alo[i], ad + 16384u);
            }
            const uint32_t bk = (((uint32_t)(2 * ks) + bcsel) << 4) ^ swz;
#pragma unroll
            for (int jj = 0; jj < 4; jj++) {
                uint32_t bh[4], bl[4];
                const uint32_t bd = st + boff[jj] + bk;
                LDSM4(bh, bd);
                LDSM4(bl, bd + 32768u);
#pragma unroll
                for (int i = 0; i < 4; i++) {
#pragma unroll
                    for (int j2 = 0; j2 < 2; j2++) {
                        float* d = acc[i][jj * 2 + j2];
                        MMA_BF16(d, ahi[i], bh + j2 * 2);
                        MMA_BF16(d, ahi[i], bl + j2 * 2);
                        MMA_BF16(d, alo[i], bh + j2 * 2);
                    }
                }
            }
        }
        __syncthreads();
        if (s + 2 < nst) LOAD_STAGE(s + 2);
    }

    // ---- epilogue ----
    const int g = lane >> 2, tig = lane & 3;
    float bv[8][2];
#pragma unroll
    for (int j = 0; j < 8; j++) {
        const int n = bn + wn * 64 + j * 8 + tig * 2;
        bv[j][0] = bias ? bias[n] : 0.f;
        bv[j][1] = bias ? bias[n + 1] : 0.f;
    }
#pragma unroll
    for (int i = 0; i < 4; i++) {
        const long long m0 = bm + wm * 64 + i * 16 + g;
#pragma unroll
        for (int j = 0; j < 8; j++) {
            const int n = bn + wn * 64 + j * 8 + tig * 2;
            const float v00 = acc[i][j][0] + bv[j][0];
            const float v01 = acc[i][j][1] + bv[j][1];
            const float v10 = acc[i][j][2] + bv[j][0];
            const float v11 = acc[i][j][3] + bv[j][1];
            const long long o0 = (z * cB) + m0 * (long long)N + n;
            const long long o1 = o0 + 8LL * N;
            if (Cf) {
                *(float2*)(Cf + o0) = make_float2(v00, v01);
                *(float2*)(Cf + o1) = make_float2(v10, v11);
            } else {
                split2(v00, v01, Chi, Clo, o0);
                split2(v10, v11, Chi, Clo, o1);
            }
        }
    }
}

// ---------------- aux kernels ----------------
__global__ __launch_bounds__(256)
void split_kernel(const float4* __restrict__ in,
                  __nv_bfloat162* __restrict__ hi, __nv_bfloat162* __restrict__ lo, int n4)
{
    int i = blockIdx.x * 256 + threadIdx.x;
    if (i < n4) {
        float4 v = in[i];
        __nv_bfloat16 hx = __float2bfloat16(v.x), hy = __float2bfloat16(v.y);
        __nv_bfloat16 hz = __float2bfloat16(v.z), hw = __float2bfloat16(v.w);
        hi[2 * i]     = __halves2bfloat162(hx, hy);
        hi[2 * i + 1] = __halves2bfloat162(hz, hw);
        lo[2 * i]     = __halves2bfloat162(__float2bfloat16(v.x - __bfloat162float(hx)),
                                           __float2bfloat16(v.y - __bfloat162float(hy)));
        lo[2 * i + 1] = __halves2bfloat162(__float2bfloat16(v.z - __bfloat162float(hz)),
                                           __float2bfloat16(v.w - __bfloat162float(hw)));
    }
}

// row softmax over 1024 columns, fp32 in place
__global__ __launch_bounds__(256)
void softmax_rows_1024(float* __restrict__ X)
{
    float* p = X + (long long)blockIdx.x * 1024;
    const int t = threadIdx.x;
    __shared__ float red[256];
    float v[4];
#pragma unroll
    for (int j = 0; j < 4; j++) v[j] = p[t + 256 * j];
    float mx = fmaxf(fmaxf(v[0], v[1]), fmaxf(v[2], v[3]));
    red[t] = mx; __syncthreads();
    for (int s = 128; s > 0; s >>= 1) { if (t < s) red[t] = fmaxf(red[t], red[t + s]); __syncthreads(); }
    mx = red[0]; __syncthreads();
    float s = 0.f;
#pragma unroll
    for (int j = 0; j < 4; j++) { v[j] = __expf(v[j] - mx); s += v[j]; }
    red[t] = s; __syncthreads();
    for (int s2 = 128; s2 > 0; s2 >>= 1) { if (t < s2) red[t] += red[t + s2]; __syncthreads(); }
    const float inv = 1.f / red[0];
#pragma unroll
    for (int j = 0; j < 4; j++) p[t + 256 * j] = v[j] * inv;
}

// column softmax over T_kv, reads fp32, writes split hi/lo. grid (1024/32, NB)
__global__ __launch_bounds__(256)
void softmax_cols_split(const float* __restrict__ X,
                        __nv_bfloat16* __restrict__ Phi, __nv_bfloat16* __restrict__ Plo)
{
    const int tx = threadIdx.x & 31;
    const int ty = threadIdx.x >> 5;
    const int c = blockIdx.x * 32 + tx;
    const long long zoff = (long long)blockIdx.y * T_SEQ * D_MODEL;
    const float* base = X + zoff + c;

    float mx = -1e30f, s = 0.f;
    for (int r = ty; r < T_SEQ; r += 8) {
        float x = base[(long long)r * D_MODEL];
        if (x > mx) { s = s * __expf(mx - x) + 1.f; mx = x; }
        else        { s += __expf(x - mx); }
    }
    __shared__ float smx[8][32], ssm[8][32];
    smx[ty][tx] = mx; ssm[ty][tx] = s;
    __syncthreads();
    if (ty == 0) {
        float M = smx[0][tx];
#pragma unroll
        for (int k = 1; k < 8; k++) M = fmaxf(M, smx[k][tx]);
        float S = 0.f;
#pragma unroll
        for (int k = 0; k < 8; k++) S += ssm[k][tx] * __expf(smx[k][tx] - M);
        smx[0][tx] = M; ssm[0][tx] = 1.f / S;
    }
    __syncthreads();
    const float M = smx[0][tx], inv = ssm[0][tx];
    for (int r = ty; r < T_SEQ; r += 8) {
        const long long o = zoff + (long long)r * D_MODEL + c;
        float p = __expf(base[(long long)r * D_MODEL] - M) * inv;
        __nv_bfloat16 h = __float2bfloat16(p);
        Phi[o] = h;
        Plo[o] = __float2bfloat16(p - __bfloat162float(h));
    }
}

// per-batch transpose [2048,1024] fp32 -> [1024,2048] split hi/lo
__global__ __launch_bounds__(256)
void transpose_split_kernel(const float* __restrict__ in,
                            __nv_bfloat16* __restrict__ hi, __nv_bfloat16* __restrict__ lo)
{
    __shared__ float t[32][33];
    const long long zoff = (long long)blockIdx.z * T_SEQ * D_MODEL;
    const float* I = in + zoff;
    const int c0 = blockIdx.x * 32, r0 = blockIdx.y * 32;
    const int tx = threadIdx.x & 31, ty = threadIdx.x >> 5;
#pragma unroll
    for (int j = 0; j < 32; j += 8)
        t[ty + j][tx] = I[(long long)(r0 + ty + j) * D_MODEL + c0 + tx];
    __syncthreads();
#pragma unroll
    for (int j = 0; j < 32; j += 8) {
        float v = t[tx][ty + j];
        const long long o = zoff + (long long)(c0 + ty + j) * T_SEQ + r0 + tx;
        __nv_bfloat16 h = __float2bfloat16(v);
        hi[o] = h;
        lo[o] = __float2bfloat16(v - __bfloat162float(h));
    }
}

// ---------------- host launcher ----------------
extern "C" void kernel_launch(void* const* d_in, const int* in_sizes, int n_in,
                              void* d_out, int out_size)
{
    const float* latent = (const float*)d_in[0];
    const float* input  = (const float*)d_in[1];
    const float* Wl = (const float*)d_in[2];
    const float* bl = (const float*)d_in[3];
    const float* Wu = (const float*)d_in[4];
    const float* bu = (const float*)d_in[5];
    const float* WA = (const float*)d_in[6];
    const float* bA = (const float*)d_in[7];
    const float* WV = (const float*)d_in[8];
    const float* bV = (const float*)d_in[9];
    const float* Wo = (const float*)d_in[10];
    const float* bo = (const float*)d_in[11];
    float* out = (float*)d_out;

    __nv_bfloat16 *lat_hi, *lat_lo, *in_hi, *in_lo, *w_hi, *w_lo;
    __nv_bfloat16 *p1_hi, *p1_lo, *lt_hi, *lt_lo, *ov_hi, *ov_lo;
    __nv_bfloat16 *mm_hi, *mm_lo, *pa_hi, *pa_lo;
    float* f1;
    cudaGetSymbolAddress((void**)&lat_hi, g_lat_hi);
    cudaGetSymbolAddress((void**)&lat_lo, g_lat_lo);
    cudaGetSymbolAddress((void**)&in_hi,  g_in_hi);
    cudaGetSymbolAddress((void**)&in_lo,  g_in_lo);
    cudaGetSymbolAddress((void**)&w_hi,   g_w_hi);
    cudaGetSymbolAddress((void**)&w_lo,   g_w_lo);
    cudaGetSymbolAddress((void**)&p1_hi,  g_p1_hi);
    cudaGetSymbolAddress((void**)&p1_lo,  g_p1_lo);
    cudaGetSymbolAddress((void**)&lt_hi,  g_lt_hi);
    cudaGetSymbolAddress((void**)&lt_lo,  g_lt_lo);
    cudaGetSymbolAddress((void**)&ov_hi,  g_ov_hi);
    cudaGetSymbolAddress((void**)&ov_lo,  g_ov_lo);
    cudaGetSymbolAddress((void**)&mm_hi,  g_mm_hi);
    cudaGetSymbolAddress((void**)&mm_lo,  g_mm_lo);
    cudaGetSymbolAddress((void**)&pa_hi,  g_pa_hi);
    cudaGetSymbolAddress((void**)&pa_lo,  g_pa_lo);
    cudaGetSymbolAddress((void**)&f1,     g_f1);

    cudaFuncSetAttribute(gemm_bf16x3,
                         cudaFuncAttributeMaxDynamicSharedMemorySize, SMEM_BYTES);

    const int D = D_MODEL;
    const int NW = D * D;
    const int NACT = MTOT * D;

    // splits of inputs
    split_kernel<<<NACT / 4 / 256, 256>>>((const float4*)latent,
                                          (__nv_bfloat162*)lat_hi, (__nv_bfloat162*)lat_lo, NACT / 4);
    split_kernel<<<NACT / 4 / 256, 256>>>((const float4*)input,
                                          (__nv_bfloat162*)in_hi, (__nv_bfloat162*)in_lo, NACT / 4);
    // all 5 weights are contiguous inputs? no — split individually into slots
    split_kernel<<<NW / 4 / 256, 256>>>((const float4*)Wl,
                                        (__nv_bfloat162*)(w_hi + 0 * NW), (__nv_bfloat162*)(w_lo + 0 * NW), NW / 4);
    split_kernel<<<NW / 4 / 256, 256>>>((const float4*)Wu,
                                        (__nv_bfloat162*)(w_hi + 1 * NW), (__nv_bfloat162*)(w_lo + 1 * NW), NW / 4);
    split_kernel<<<NW / 4 / 256, 256>>>((const float4*)WA,
                                        (__nv_bfloat162*)(w_hi + 2 * NW), (__nv_bfloat162*)(w_lo + 2 * NW), NW / 4);
    split_kernel<<<NW / 4 / 256, 256>>>((const float4*)WV,
                                        (__nv_bfloat162*)(w_hi + 3 * NW), (__nv_bfloat162*)(w_lo + 3 * NW), NW / 4);
    split_kernel<<<NW / 4 / 256, 256>>>((const float4*)Wo,
                                        (__nv_bfloat162*)(w_hi + 4 * NW), (__nv_bfloat162*)(w_lo + 4 * NW), NW / 4);

    dim3 thr(256);
    dim3 gProj(D / 256, MTOT / 128, 1);       // (4, 64)

    // G1: emb0 = latent @ Wl^T + bl -> p1 pair
    gemm_bf16x3<<<gProj, thr, SMEM_BYTES>>>(lat_hi, lat_lo, w_hi + 0 * NW, w_lo + 0 * NW,
                                            bl, nullptr, p1_hi, p1_lo, D, D, 0, 0, 0);
    // G2: s1 = emb0 @ Wu^T + bu -> f1 fp32
    gemm_bf16x3<<<gProj, thr, SMEM_BYTES>>>(p1_hi, p1_lo, w_hi + 1 * NW, w_lo + 1 * NW,
                                            bu, f1, nullptr, nullptr, D, D, 0, 0, 0);
    softmax_rows_1024<<<MTOT, 256>>>(f1);
    // L^T -> lt pair
    transpose_split_kernel<<<dim3(D / 32, T_SEQ / 32, NB), 256>>>(f1, lt_hi, lt_lo);

    // G3: Dm = input @ WA^T + bA -> p1 pair (emb0 dead)
    gemm_bf16x3<<<gProj, thr, SMEM_BYTES>>>(in_hi, in_lo, w_hi + 2 * NW, w_lo + 2 * NW,
                                            bA, nullptr, p1_hi, p1_lo, D, D, 0, 0, 0);
    // G4: S2 = Dm @ WV^T + bV -> f1 fp32
    gemm_bf16x3<<<gProj, thr, SMEM_BYTES>>>(p1_hi, p1_lo, w_hi + 3 * NW, w_lo + 3 * NW,
                                            bV, f1, nullptr, nullptr, D, D, 0, 0, 0);
    softmax_cols_split<<<dim3(D / 32, NB), 256>>>(f1, pa_hi, pa_lo);

    // G5: ov = latent @ Wo^T + bo -> f1 fp32 ; transpose -> ov pair
    gemm_bf16x3<<<gProj, thr, SMEM_BYTES>>>(lat_hi, lat_lo, w_hi + 4 * NW, w_lo + 4 * NW,
                                            bo, f1, nullptr, nullptr, D, D, 0, 0, 0);
    transpose_split_kernel<<<dim3(D / 32, T_SEQ / 32, NB), 256>>>(f1, ov_hi, ov_lo);

    // G6: M^T[b] = ovT[b] @ LT[b]^T  (M=1024, N=1024, K=2048) -> mm pair
    gemm_bf16x3<<<dim3(D / 256, D / 128, NB), thr, SMEM_BYTES>>>(
        ov_hi, ov_lo, lt_hi, lt_lo, nullptr, nullptr, mm_hi, mm_lo,
        D, T_SEQ, (long long)D * T_SEQ, (long long)D * T_SEQ, (long long)D * D);

    // G7: o[b] = A_sm[b] @ (M^T[b])^T  (M=2048, N=1024, K=1024) -> d_out fp32
    gemm_bf16x3<<<dim3(D / 256, T_SEQ / 128, NB), thr, SMEM_BYTES>>>(
        pa_hi, pa_lo, mm_hi, mm_lo, nullptr, out, nullptr, nullptr,
        D, D, (long long)T_SEQ * D, (long long)D * D, (long long)T_SEQ * D);
}

// round 4
// speedup vs baseline: 6.1232x; 1.3917x over previous
#include <cuda_runtime.h>
#include <cuda_fp16.h>
#include <cstdint>
#include <math.h>

// ITAttention on GB300, sm_103 baseline ISA (no tcgen05 on this ptxas target).
// mma.sync.m16n8k16 fp16 HMMA with asymmetric split:
//   C = (A) @ (B_hi + B_lo)^T  -> 2 MMAs per K-chunk
// A is a single RN fp16 (error ~2^-12), B is an fp16 hi/lo pair (~exact).
// Pipeline (associativity-restructured): o = A_sm @ (L^T @ ov)

#define D_MODEL 1024
#define T_SEQ   2048
#define NB      4
#define MTOT    (NB * T_SEQ)       // 8192

// ---------------- scratch (no allocation allowed) ----------------
__device__ __align__(256) __half g_lat_h[MTOT * D_MODEL];
__device__ __align__(256) __half g_in_h [MTOT * D_MODEL];
__device__ __align__(256) __half g_w_hi [5 * D_MODEL * D_MODEL];
__device__ __align__(256) __half g_w_lo [5 * D_MODEL * D_MODEL];
__device__ __align__(256) __half g_p1_h [MTOT * D_MODEL];          // emb0 -> Dm (single)
__device__ __align__(256) __half g_lt_hi[MTOT * D_MODEL];          // L^T pair [B,1024,2048]
__device__ __align__(256) __half g_lt_lo[MTOT * D_MODEL];
__device__ __align__(256) __half g_ov_h [MTOT * D_MODEL];          // ov^T single [B,1024,2048]
__device__ __align__(256) __half g_mm_hi[NB * D_MODEL * D_MODEL];  // M^T pair
__device__ __align__(256) __half g_mm_lo[NB * D_MODEL * D_MODEL];
__device__ __align__(256) __half g_pa_h [MTOT * D_MODEL];          // softmaxed A (single)
__device__ __align__(256) float  g_f1  [MTOT * D_MODEL];           // fp32 staging

// ---------------- helpers ----------------
__device__ __forceinline__ uint32_t smem_u32(const void* p) {
    uint32_t a;
    asm("{ .reg .u64 t; cvta.to.shared.u64 t, %1; cvt.u32.u64 %0, t; }" : "=r"(a) : "l"(p));
    return a;
}
__device__ __forceinline__ void cp16(uint32_t dst, const void* src) {
    asm volatile("cp.async.cg.shared.global [%0], [%1], 16;" :: "r"(dst), "l"(src) : "memory");
}
__device__ __forceinline__ void cp_commit() {
    asm volatile("cp.async.commit_group;" ::: "memory");
}

#define LDSM4(r, addr)                                                            \
    asm volatile("ldmatrix.sync.aligned.m8n8.x4.shared.b16 {%0,%1,%2,%3}, [%4];"  \
                 : "=r"((r)[0]), "=r"((r)[1]), "=r"((r)[2]), "=r"((r)[3])         \
                 : "r"(addr))

#define MMA_F16(d, a, b)                                                           \
    asm volatile("mma.sync.aligned.m16n8k16.row.col.f32.f16.f16.f32 "              \
                 "{%0,%1,%2,%3}, {%4,%5,%6,%7}, {%8,%9}, {%0,%1,%2,%3};"           \
                 : "+f"((d)[0]), "+f"((d)[1]), "+f"((d)[2]), "+f"((d)[3])          \
                 : "r"((a)[0]), "r"((a)[1]), "r"((a)[2]), "r"((a)[3]),             \
                   "r"((b)[0]), "r"((b)[1]))

// ---------------- fp16 asymmetric GEMM: C[M,N] = A @ (Bhi+Blo)^T ----------------
// A [M,K] fp16 single, B [N,K] fp16 pair, K contiguous. BM=128, BN=256, BK=64.
// 256 threads = 8 warps, 2x4, warp tile 64x64.
// smem/stage: A 16K | Bhi 32K | Blo 32K = 80KB; 2 stages = 160KB.
#define STG_BYTES 81920u
#define SMEM_BYTES (2 * 81920)

#define LOAD_STAGE(sidx) do {                                                        \
    const uint32_t base_ = sb + (uint32_t)((sidx) & 1) * STG_BYTES;                  \
    const int k0_ = (sidx) * 64;                                                     \
    _Pragma("unroll")                                                                \
    for (int t_ = 0; t_ < 4; t_++) {                                                 \
        int idx_ = tid + 256 * t_;                                                   \
        int r_ = idx_ >> 3, c_ = idx_ & 7;                                           \
        uint32_t sm_ = base_ + (uint32_t)r_ * 128u +                                 \
                       ((uint32_t)(c_ * 16) ^ ((uint32_t)(r_ & 7) * 16u));           \
        cp16(sm_, Ah + (size_t)r_ * K + k0_ + c_ * 8);                               \
    }                                                                                \
    _Pragma("unroll")                                                                \
    for (int t_ = 0; t_ < 8; t_++) {                                                 \
        int idx_ = tid + 256 * t_;                                                   \
        int r_ = idx_ >> 3, c_ = idx_ & 7;                                           \
        uint32_t sm_ = base_ + 16384u + (uint32_t)r_ * 128u +                        \
                       ((uint32_t)(c_ * 16) ^ ((uint32_t)(r_ & 7) * 16u));           \
        size_t go_ = (size_t)r_ * K + k0_ + c_ * 8;                                  \
        cp16(sm_, Bhi + go_);                                                        \
        cp16(sm_ + 32768u, Blo + go_);                                               \
    }                                                                                \
    cp_commit();                                                                     \
} while (0)

__global__ void __launch_bounds__(256, 1)
gemm_f16asym(const __half* __restrict__ Ah,
             const __half* __restrict__ Bhi, const __half* __restrict__ Blo,
             const float* __restrict__ bias,
             float* __restrict__ Cf,            // mode fp32
             __half* __restrict__ Ch,           // mode single half
             __half* __restrict__ Phi, __half* __restrict__ Plo, // mode pair
             int N, int K,
             long long aB, long long bB, long long cB)
{
    extern __shared__ char smem[];
    const uint32_t sb = smem_u32(smem);
    const int tid = threadIdx.x, lane = tid & 31, wid = tid >> 5;
    const int wm = wid >> 2;            // 0..1
    const int wn = wid & 3;             // 0..3
    const long long z = blockIdx.z;
    const int bm = blockIdx.y * 128, bn = blockIdx.x * 256;

    Ah  += z * aB + (long long)bm * K;
    Bhi += z * bB + (long long)bn * K;
    Blo += z * bB + (long long)bn * K;

    const int nst = K >> 6;

    LOAD_STAGE(0);
    LOAD_STAGE(1);

    const uint32_t swz = ((uint32_t)(lane & 7)) << 4;
    const uint32_t acsel = (uint32_t)(lane >> 4);
    uint32_t aoff[4];
#pragma unroll
    for (int i = 0; i < 4; i++)
        aoff[i] = (uint32_t)(wm * 64 + i * 16 + (lane & 15)) * 128u;
    const uint32_t bcsel = (uint32_t)((lane >> 3) & 1);
    const int brow = (lane & 7) + ((lane >> 4) << 3);
    uint32_t boff[4];
#pragma unroll
    for (int jj = 0; jj < 4; jj++)
        boff[jj] = 16384u + (uint32_t)(wn * 64 + jj * 16 + brow) * 128u;

    float acc[4][8][4];
#pragma unroll
    for (int i = 0; i < 4; i++)
#pragma unroll
        for (int j = 0; j < 8; j++)
#pragma unroll
            for (int r = 0; r < 4; r++) acc[i][j][r] = 0.f;

    for (int s = 0; s < nst; s++) {
        if (s + 1 < nst) asm volatile("cp.async.wait_group 1;" ::: "memory");
        else             asm volatile("cp.async.wait_group 0;" ::: "memory");
        __syncthreads();
        const uint32_t st = sb + (uint32_t)(s & 1) * STG_BYTES;

#pragma unroll
        for (int ks = 0; ks < 4; ks++) {
            uint32_t af[4][4];
            const uint32_t ak = (((uint32_t)(2 * ks) + acsel) << 4) ^ swz;
#pragma unroll
            for (int i = 0; i < 4; i++)
                LDSM4(af[i], st + aoff[i] + ak);
            const uint32_t bk = (((uint32_t)(2 * ks) + bcsel) << 4) ^ swz;
#pragma unroll
            for (int jj = 0; jj < 4; jj++) {
                uint32_t bh[4], bl[4];
                const uint32_t bd = st + boff[jj] + bk;
                LDSM4(bh, bd);
                LDSM4(bl, bd + 32768u);
#pragma unroll
                for (int i = 0; i < 4; i++) {
#pragma unroll
                    for (int j2 = 0; j2 < 2; j2++) {
                        float* d = acc[i][jj * 2 + j2];
                        MMA_F16(d, af[i], bh + j2 * 2);
                        MMA_F16(d, af[i], bl + j2 * 2);
                    }
                }
            }
        }
        __syncthreads();
        if (s + 2 < nst) LOAD_STAGE(s + 2);
    }

    // ---- epilogue ----
    const int g = lane >> 2, tig = lane & 3;
    float bv[8][2];
#pragma unroll
    for (int j = 0; j < 8; j++) {
        const int n = bn + wn * 64 + j * 8 + tig * 2;
        bv[j][0] = bias ? bias[n] : 0.f;
        bv[j][1] = bias ? bias[n + 1] : 0.f;
    }
#pragma unroll
    for (int i = 0; i < 4; i++) {
        const long long m0 = bm + wm * 64 + i * 16 + g;
#pragma unroll
        for (int j = 0; j < 8; j++) {
            const int n = bn + wn * 64 + j * 8 + tig * 2;
#pragma unroll
            for (int h = 0; h < 2; h++) {
                const float v0 = acc[i][j][2 * h]     + bv[j][0];
                const float v1 = acc[i][j][2 * h + 1] + bv[j][1];
                const long long o = (z * cB) + (m0 + 8 * h) * (long long)N + n;
                if (Cf) {
                    *(float2*)(Cf + o) = make_float2(v0, v1);
                } else if (Ch) {
                    *(__half2*)(Ch + o) = __floats2half2_rn(v0, v1);
                } else {
                    __half h0 = __float2half(v0), h1 = __float2half(v1);
                    *(__half2*)(Phi + o) = __halves2half2(h0, h1);
                    *(__half2*)(Plo + o) = __floats2half2_rn(v0 - __half2float(h0),
                                                            v1 - __half2float(h1));
                }
            }
        }
    }
}

// ---------------- aux kernels ----------------
__global__ __launch_bounds__(256)
void tohalf_kernel(const float4* __restrict__ in, __half2* __restrict__ out, int n4)
{
    int i = blockIdx.x * 256 + threadIdx.x;
    if (i < n4) {
        float4 v = in[i];
        out[2 * i]     = __floats2half2_rn(v.x, v.y);
        out[2 * i + 1] = __floats2half2_rn(v.z, v.w);
    }
}

__global__ __launch_bounds__(256)
void splitpair_kernel(const float4* __restrict__ in,
                      __half2* __restrict__ hi, __half2* __restrict__ lo, int n4)
{
    int i = blockIdx.x * 256 + threadIdx.x;
    if (i < n4) {
        float4 v = in[i];
        __half hx = __float2half(v.x), hy = __float2half(v.y);
        __half hz = __float2half(v.z), hw = __float2half(v.w);
        hi[2 * i]     = __halves2half2(hx, hy);
        hi[2 * i + 1] = __halves2half2(hz, hw);
        lo[2 * i]     = __floats2half2_rn(v.x - __half2float(hx), v.y - __half2float(hy));
        lo[2 * i + 1] = __floats2half2_rn(v.z - __half2float(hz), v.w - __half2float(hw));
    }
}

// row softmax over 1024 columns, fp32 in place
__global__ __launch_bounds__(256)
void softmax_rows_1024(float* __restrict__ X)
{
    float* p = X + (long long)blockIdx.x * 1024;
    const int t = threadIdx.x;
    __shared__ float red[256];
    float v[4];
#pragma unroll
    for (int j = 0; j < 4; j++) v[j] = p[t + 256 * j];
    float mx = fmaxf(fmaxf(v[0], v[1]), fmaxf(v[2], v[3]));
    red[t] = mx; __syncthreads();
    for (int s = 128; s > 0; s >>= 1) { if (t < s) red[t] = fmaxf(red[t], red[t + s]); __syncthreads(); }
    mx = red[0]; __syncthreads();
    float s = 0.f;
#pragma unroll
    for (int j = 0; j < 4; j++) { v[j] = __expf(v[j] - mx); s += v[j]; }
    red[t] = s; __syncthreads();
    for (int s2 = 128; s2 > 0; s2 >>= 1) { if (t < s2) red[t] += red[t + s2]; __syncthreads(); }
    const float inv = 1.f / red[0];
#pragma unroll
    for (int j = 0; j < 4; j++) p[t + 256 * j] = v[j] * inv;
}

// column softmax over T_kv, fp32 in -> single fp16 out. grid (1024/32, NB)
__global__ __launch_bounds__(256)
void softmax_cols_half(const float* __restrict__ X, __half* __restrict__ P)
{
    const int tx = threadIdx.x & 31;
    const int ty = threadIdx.x >> 5;
    const int c = blockIdx.x * 32 + tx;
    const long long zoff = (long long)blockIdx.y * T_SEQ * D_MODEL;
    const float* base = X + zoff + c;

    float mx = -1e30f, s = 0.f;
    for (int r = ty; r < T_SEQ; r += 8) {
        float x = base[(long long)r * D_MODEL];
        if (x > mx) { s = s * __expf(mx - x) + 1.f; mx = x; }
        else        { s += __expf(x - mx); }
    }
    __shared__ float smx[8][32], ssm[8][32];
    smx[ty][tx] = mx; ssm[ty][tx] = s;
    __syncthreads();
    if (ty == 0) {
        float M = smx[0][tx];
#pragma unroll
        for (int k = 1; k < 8; k++) M = fmaxf(M, smx[k][tx]);
        float S = 0.f;
#pragma unroll
        for (int k = 0; k < 8; k++) S += ssm[k][tx] * __expf(smx[k][tx] - M);
        smx[0][tx] = M; ssm[0][tx] = 1.f / S;
    }
    __syncthreads();
    const float M = smx[0][tx], inv = ssm[0][tx];
    for (int r = ty; r < T_SEQ; r += 8) {
        const long long o = zoff + (long long)r * D_MODEL + c;
        P[o] = __float2half(__expf(base[(long long)r * D_MODEL] - M) * inv);
    }
}

// per-batch transpose [2048,1024] fp32 -> [1024,2048] fp16 pair
__global__ __launch_bounds__(256)
void transpose_pair_kernel(const float* __restrict__ in,
                           __half* __restrict__ hi, __half* __restrict__ lo)
{
    __shared__ float t[32][33];
    const long long zoff = (long long)blockIdx.z * T_SEQ * D_MODEL;
    const float* I = in + zoff;
    const int c0 = blockIdx.x * 32, r0 = blockIdx.y * 32;
    const int tx = threadIdx.x & 31, ty = threadIdx.x >> 5;
#pragma unroll
    for (int j = 0; j < 32; j += 8)
        t[ty + j][tx] = I[(long long)(r0 + ty + j) * D_MODEL + c0 + tx];
    __syncthreads();
#pragma unroll
    for (int j = 0; j < 32; j += 8) {
        float v = t[tx][ty + j];
        const long long o = zoff + (long long)(c0 + ty + j) * T_SEQ + r0 + tx;
        __half h = __float2half(v);
        hi[o] = h;
        lo[o] = __float2half(v - __half2float(h));
    }
}

// per-batch transpose [2048,1024] fp32 -> [1024,2048] single fp16
__global__ __launch_bounds__(256)
void transpose_half_kernel(const float* __restrict__ in, __half* __restrict__ out)
{
    __shared__ float t[32][33];
    const long long zoff = (long long)blockIdx.z * T_SEQ * D_MODEL;
    const float* I = in + zoff;
    const int c0 = blockIdx.x * 32, r0 = blockIdx.y * 32;
    const int tx = threadIdx.x & 31, ty = threadIdx.x >> 5;
#pragma unroll
    for (int j = 0; j < 32; j += 8)
        t[ty + j][tx] = I[(long long)(r0 + ty + j) * D_MODEL + c0 + tx];
    __syncthreads();
#pragma unroll
    for (int j = 0; j < 32; j += 8)
        out[zoff + (long long)(c0 + ty + j) * T_SEQ + r0 + tx] = __float2half(t[tx][ty + j]);
}

// ---------------- host launcher ----------------
extern "C" void kernel_launch(void* const* d_in, const int* in_sizes, int n_in,
                              void* d_out, int out_size)
{
    const float* latent = (const float*)d_in[0];
    const float* input  = (const float*)d_in[1];
    const float* Wl = (const float*)d_in[2];
    const float* bl = (const float*)d_in[3];
    const float* Wu = (const float*)d_in[4];
    const float* bu = (const float*)d_in[5];
    const float* WA = (const float*)d_in[6];
    const float* bA = (const float*)d_in[7];
    const float* WV = (const float*)d_in[8];
    const float* bV = (const float*)d_in[9];
    const float* Wo = (const float*)d_in[10];
    const float* bo = (const float*)d_in[11];
    float* out = (float*)d_out;

    __half *lat_h, *in_h, *w_hi, *w_lo, *p1_h, *lt_hi, *lt_lo, *ov_h, *mm_hi, *mm_lo, *pa_h;
    float* f1;
    cudaGetSymbolAddress((void**)&lat_h, g_lat_h);
    cudaGetSymbolAddress((void**)&in_h,  g_in_h);
    cudaGetSymbolAddress((void**)&w_hi,  g_w_hi);
    cudaGetSymbolAddress((void**)&w_lo,  g_w_lo);
    cudaGetSymbolAddress((void**)&p1_h,  g_p1_h);
    cudaGetSymbolAddress((void**)&lt_hi, g_lt_hi);
    cudaGetSymbolAddress((void**)&lt_lo, g_lt_lo);
    cudaGetSymbolAddress((void**)&ov_h,  g_ov_h);
    cudaGetSymbolAddress((void**)&mm_hi, g_mm_hi);
    cudaGetSymbolAddress((void**)&mm_lo, g_mm_lo);
    cudaGetSymbolAddress((void**)&pa_h,  g_pa_h);
    cudaGetSymbolAddress((void**)&f1,    g_f1);

    cudaFuncSetAttribute(gemm_f16asym,
                         cudaFuncAttributeMaxDynamicSharedMemorySize, SMEM_BYTES);

    const int D = D_MODEL;
    const int NW = D * D;
    const int NACT = MTOT * D;

    // operand prep
    tohalf_kernel<<<NACT / 4 / 256, 256>>>((const float4*)latent, (__half2*)lat_h, NACT / 4);
    tohalf_kernel<<<NACT / 4 / 256, 256>>>((const float4*)input,  (__half2*)in_h,  NACT / 4);
    splitpair_kernel<<<NW / 4 / 256, 256>>>((const float4*)Wl,
                                            (__half2*)(w_hi + 0 * NW), (__half2*)(w_lo + 0 * NW), NW / 4);
    splitpair_kernel<<<NW / 4 / 256, 256>>>((const float4*)Wu,
                                            (__half2*)(w_hi + 1 * NW), (__half2*)(w_lo + 1 * NW), NW / 4);
    splitpair_kernel<<<NW / 4 / 256, 256>>>((const float4*)WA,
                                            (__half2*)(w_hi + 2 * NW), (__half2*)(w_lo + 2 * NW), NW / 4);
    splitpair_kernel<<<NW / 4 / 256, 256>>>((const float4*)WV,
                                            (__half2*)(w_hi + 3 * NW), (__half2*)(w_lo + 3 * NW), NW / 4);
    splitpair_kernel<<<NW / 4 / 256, 256>>>((const float4*)Wo,
                                            (__half2*)(w_hi + 4 * NW), (__half2*)(w_lo + 4 * NW), NW / 4);

    dim3 thr(256);
    dim3 gProj(D / 256, MTOT / 128, 1);       // (4, 64)

    // G1: emb0 = latent @ Wl^T + bl -> p1 single half
    gemm_f16asym<<<gProj, thr, SMEM_BYTES>>>(lat_h, w_hi + 0 * NW, w_lo + 0 * NW, bl,
                                             nullptr, p1_h, nullptr, nullptr, D, D, 0, 0, 0);
    // G2: s1 = emb0 @ Wu^T + bu -> f1 fp32
    gemm_f16asym<<<gProj, thr, SMEM_BYTES>>>(p1_h, w_hi + 1 * NW, w_lo + 1 * NW, bu,
                                             f1, nullptr, nullptr, nullptr, D, D, 0, 0, 0);
    softmax_rows_1024<<<MTOT, 256>>>(f1);
    transpose_pair_kernel<<<dim3(D / 32, T_SEQ / 32, NB), 256>>>(f1, lt_hi, lt_lo);

    // G3: Dm = input @ WA^T + bA -> p1 single half
    gemm_f16asym<<<gProj, thr, SMEM_BYTES>>>(in_h, w_hi + 2 * NW, w_lo + 2 * NW, bA,
                                             nullptr, p1_h, nullptr, nullptr, D, D, 0, 0, 0);
    // G4: S2 = Dm @ WV^T + bV -> f1 fp32
    gemm_f16asym<<<gProj, thr, SMEM_BYTES>>>(p1_h, w_hi + 3 * NW, w_lo + 3 * NW, bV,
                                             f1, nullptr, nullptr, nullptr, D, D, 0, 0, 0);
    softmax_cols_half<<<dim3(D / 32, NB), 256>>>(f1, pa_h);

    // G5: ov = latent @ Wo^T + bo -> f1 fp32 ; transpose -> ov single half
    gemm_f16asym<<<gProj, thr, SMEM_BYTES>>>(lat_h, w_hi + 4 * NW, w_lo + 4 * NW, bo,
                                             f1, nullptr, nullptr, nullptr, D, D, 0, 0, 0);
    transpose_half_kernel<<<dim3(D / 32, T_SEQ / 32, NB), 256>>>(f1, ov_h);

    // G6: M^T[b] = ovT[b] @ LT[b]^T  (M=1024, N=1024, K=2048) -> mm pair
    gemm_f16asym<<<dim3(D / 256, D / 128, NB), thr, SMEM_BYTES>>>(
        ov_h, lt_hi, lt_lo, nullptr, nullptr, nullptr, mm_hi, mm_lo,
        D, T_SEQ, (long long)D * T_SEQ, (long long)D * T_SEQ, (long long)D * D);

    // G7: o[b] = A_sm[b] @ (M^T[b])^T  (M=2048, N=1024, K=1024) -> d_out fp32
    gemm_f16asym<<<dim3(D / 256, T_SEQ / 128, NB), thr, SMEM_BYTES>>>(
        pa_h, mm_hi, mm_lo, nullptr, out, nullptr, nullptr, nullptr,
        D, D, (long long)T_SEQ * D, (long long)D * D, (long long)T_SEQ * D);
}

// round 5
// speedup vs baseline: 9.5764x; 1.5640x over previous
#include <cuda_runtime.h>
#include <cuda_fp16.h>
#include <cstdint>
#include <math.h>

// ITAttention on GB300, sm_103 baseline ISA. mma.sync.m16n8k16 fp16 HMMA,
// single-fp16 operands (1 MMA per product), fp32 accumulate.
// Pipeline (associativity-restructured): o = A_sm @ (L^T @ ov)

#define D_MODEL 1024
#define T_SEQ   2048
#define NB      4
#define MTOT    (NB * T_SEQ)       // 8192

// ---------------- scratch (no allocation allowed) ----------------
__device__ __align__(256) __half g_lat_h[MTOT * D_MODEL];
__device__ __align__(256) __half g_in_h [MTOT * D_MODEL];
__device__ __align__(256) __half g_w_h  [5 * D_MODEL * D_MODEL];
__device__ __align__(256) __half g_p1_h [MTOT * D_MODEL];          // emb0 -> Dm
__device__ __align__(256) __half g_lt_h [MTOT * D_MODEL];          // L^T [B,1024,2048]
__device__ __align__(256) __half g_ov_h [MTOT * D_MODEL];          // ov^T [B,1024,2048]
__device__ __align__(256) __half g_mm_h [NB * D_MODEL * D_MODEL];  // M^T
__device__ __align__(256) __half g_pa_h [MTOT * D_MODEL];          // softmaxed A
__device__ __align__(256) float  g_f1  [MTOT * D_MODEL];           // fp32 staging

// ---------------- helpers ----------------
__device__ __forceinline__ uint32_t smem_u32(const void* p) {
    uint32_t a;
    asm("{ .reg .u64 t; cvta.to.shared.u64 t, %1; cvt.u32.u64 %0, t; }" : "=r"(a) : "l"(p));
    return a;
}
__device__ __forceinline__ void cp16(uint32_t dst, const void* src) {
    asm volatile("cp.async.cg.shared.global [%0], [%1], 16;" :: "r"(dst), "l"(src) : "memory");
}
__device__ __forceinline__ void cp_commit() {
    asm volatile("cp.async.commit_group;" ::: "memory");
}

#define LDSM4(r, addr)                                                            \
    asm volatile("ldmatrix.sync.aligned.m8n8.x4.shared.b16 {%0,%1,%2,%3}, [%4];"  \
                 : "=r"((r)[0]), "=r"((r)[1]), "=r"((r)[2]), "=r"((r)[3])         \
                 : "r"(addr))

#define MMA_F16(d, a, b)                                                           \
    asm volatile("mma.sync.aligned.m16n8k16.row.col.f32.f16.f16.f32 "              \
                 "{%0,%1,%2,%3}, {%4,%5,%6,%7}, {%8,%9}, {%0,%1,%2,%3};"           \
                 : "+f"((d)[0]), "+f"((d)[1]), "+f"((d)[2]), "+f"((d)[3])          \
                 : "r"((a)[0]), "r"((a)[1]), "r"((a)[2]), "r"((a)[3]),             \
                   "r"((b)[0]), "r"((b)[1]))

// ---------------- fp16 GEMM: C[M,N] = A @ B^T ----------------
// A [M,K] fp16, B [N,K] fp16, K contiguous. BM=128, BN=256, BK=64.
// 256 threads = 8 warps (2x4), warp tile 64x64.
// smem/stage: A 16K | B 32K = 48KB; 4 stages = 192KB.
#define STG_BYTES 49152u
#define NSTAGE    4
#define SMEM_BYTES (NSTAGE * 49152)

#define LOAD_STAGE(sidx) do {                                                        \
    const uint32_t base_ = sb + (uint32_t)((sidx) & 3) * STG_BYTES;                  \
    const int k0_ = (sidx) * 64;                                                     \
    _Pragma("unroll")                                                                \
    for (int t_ = 0; t_ < 4; t_++) {                                                 \
        int idx_ = tid + 256 * t_;                                                   \
        int r_ = idx_ >> 3, c_ = idx_ & 7;                                           \
        uint32_t sm_ = base_ + (uint32_t)r_ * 128u +                                 \
                       ((uint32_t)(c_ * 16) ^ ((uint32_t)(r_ & 7) * 16u));           \
        cp16(sm_, Ah + (size_t)r_ * K + k0_ + c_ * 8);                               \
    }                                                                                \
    _Pragma("unroll")                                                                \
    for (int t_ = 0; t_ < 8; t_++) {                                                 \
        int idx_ = tid + 256 * t_;                                                   \
        int r_ = idx_ >> 3, c_ = idx_ & 7;                                           \
        uint32_t sm_ = base_ + 16384u + (uint32_t)r_ * 128u +                        \
                       ((uint32_t)(c_ * 16) ^ ((uint32_t)(r_ & 7) * 16u));           \
        cp16(sm_, Bh + (size_t)r_ * K + k0_ + c_ * 8);                               \
    }                                                                                \
    cp_commit();                                                                     \
} while (0)

__global__ void __launch_bounds__(256, 1)
gemm_f16(const __half* __restrict__ Ah, const __half* __restrict__ Bh,
         const float* __restrict__ bias,
         float* __restrict__ Cf,            // mode fp32 out
         __half* __restrict__ Ch,           // mode fp16 out
         int N, int K,
         long long aB, long long bB, long long cB)
{
    extern __shared__ char smem[];
    const uint32_t sb = smem_u32(smem);
    const int tid = threadIdx.x, lane = tid & 31, wid = tid >> 5;
    const int wm = wid >> 2;            // 0..1
    const int wn = wid & 3;             // 0..3
    const long long z = blockIdx.z;
    const int bm = blockIdx.y * 128, bn = blockIdx.x * 256;

    Ah += z * aB + (long long)bm * K;
    Bh += z * bB + (long long)bn * K;

    const int nst = K >> 6;

    LOAD_STAGE(0);
    LOAD_STAGE(1);
    LOAD_STAGE(2);

    const uint32_t swz = ((uint32_t)(lane & 7)) << 4;
    const uint32_t acsel = (uint32_t)(lane >> 4);
    uint32_t aoff[4];
#pragma unroll
    for (int i = 0; i < 4; i++)
        aoff[i] = (uint32_t)(wm * 64 + i * 16 + (lane & 15)) * 128u;
    const uint32_t bcsel = (uint32_t)((lane >> 3) & 1);
    const int brow = (lane & 7) + ((lane >> 4) << 3);
    uint32_t boff[4];
#pragma unroll
    for (int jj = 0; jj < 4; jj++)
        boff[jj] = 16384u + (uint32_t)(wn * 64 + jj * 16 + brow) * 128u;

    float acc[4][8][4];
#pragma unroll
    for (int i = 0; i < 4; i++)
#pragma unroll
        for (int j = 0; j < 8; j++)
#pragma unroll
            for (int r = 0; r < 4; r++) acc[i][j][r] = 0.f;

    for (int s = 0; s < nst; s++) {
        const int rem = nst - 1 - s;        // groups that will still be committed after wait
        if (rem >= 2)      asm volatile("cp.async.wait_group 2;" ::: "memory");
        else if (rem == 1) asm volatile("cp.async.wait_group 1;" ::: "memory");
        else               asm volatile("cp.async.wait_group 0;" ::: "memory");
        __syncthreads();
        // prefetch stage s+3 into the buffer freed by stage s-1 (all warps synced)
        if (s + 3 < nst) LOAD_STAGE(s + 3);

        const uint32_t st = sb + (uint32_t)(s & 3) * STG_BYTES;
#pragma unroll
        for (int ks = 0; ks < 4; ks++) {
            uint32_t af[4][4];
            const uint32_t ak = (((uint32_t)(2 * ks) + acsel) << 4) ^ swz;
#pragma unroll
            for (int i = 0; i < 4; i++)
                LDSM4(af[i], st + aoff[i] + ak);
            const uint32_t bk = (((uint32_t)(2 * ks) + bcsel) << 4) ^ swz;
#pragma unroll
            for (int jj = 0; jj < 4; jj++) {
                uint32_t bf[4];
                LDSM4(bf, st + boff[jj] + bk);
#pragma unroll
                for (int i = 0; i < 4; i++) {
                    MMA_F16(acc[i][jj * 2 + 0], af[i], bf);
                    MMA_F16(acc[i][jj * 2 + 1], af[i], bf + 2);
                }
            }
        }
    }

    // ---- epilogue ----
    const int g = lane >> 2, tig = lane & 3;
    float bv[8][2];
#pragma unroll
    for (int j = 0; j < 8; j++) {
        const int n = bn + wn * 64 + j * 8 + tig * 2;
        bv[j][0] = bias ? bias[n] : 0.f;
        bv[j][1] = bias ? bias[n + 1] : 0.f;
    }
#pragma unroll
    for (int i = 0; i < 4; i++) {
        const long long m0 = bm + wm * 64 + i * 16 + g;
#pragma unroll
        for (int j = 0; j < 8; j++) {
            const int n = bn + wn * 64 + j * 8 + tig * 2;
#pragma unroll
            for (int h = 0; h < 2; h++) {
                const float v0 = acc[i][j][2 * h]     + bv[j][0];
                const float v1 = acc[i][j][2 * h + 1] + bv[j][1];
                const long long o = (z * cB) + (m0 + 8 * h) * (long long)N + n;
                if (Cf) *(float2*)(Cf + o) = make_float2(v0, v1);
                else    *(__half2*)(Ch + o) = __floats2half2_rn(v0, v1);
            }
        }
    }
}

// ---------------- aux kernels ----------------
__global__ __launch_bounds__(256)
void tohalf_kernel(const float4* __restrict__ in, __half2* __restrict__ out, int n4)
{
    int i = blockIdx.x * 256 + threadIdx.x;
    if (i < n4) {
        float4 v = in[i];
        out[2 * i]     = __floats2half2_rn(v.x, v.y);
        out[2 * i + 1] = __floats2half2_rn(v.z, v.w);
    }
}

// row softmax over 1024 columns, fp32 in place
__global__ __launch_bounds__(256)
void softmax_rows_1024(float* __restrict__ X)
{
    float* p = X + (long long)blockIdx.x * 1024;
    const int t = threadIdx.x;
    __shared__ float red[256];
    float v[4];
#pragma unroll
    for (int j = 0; j < 4; j++) v[j] = p[t + 256 * j];
    float mx = fmaxf(fmaxf(v[0], v[1]), fmaxf(v[2], v[3]));
    red[t] = mx; __syncthreads();
    for (int s = 128; s > 0; s >>= 1) { if (t < s) red[t] = fmaxf(red[t], red[t + s]); __syncthreads(); }
    mx = red[0]; __syncthreads();
    float s = 0.f;
#pragma unroll
    for (int j = 0; j < 4; j++) { v[j] = __expf(v[j] - mx); s += v[j]; }
    red[t] = s; __syncthreads();
    for (int s2 = 128; s2 > 0; s2 >>= 1) { if (t < s2) red[t] += red[t + s2]; __syncthreads(); }
    const float inv = 1.f / red[0];
#pragma unroll
    for (int j = 0; j < 4; j++) p[t + 256 * j] = v[j] * inv;
}

// column softmax over T_kv, fp32 in -> fp16 out. grid (1024/32, NB)
__global__ __launch_bounds__(256)
void softmax_cols_half(const float* __restrict__ X, __half* __restrict__ P)
{
    const int tx = threadIdx.x & 31;
    const int ty = threadIdx.x >> 5;
    const int c = blockIdx.x * 32 + tx;
    const long long zoff = (long long)blockIdx.y * T_SEQ * D_MODEL;
    const float* base = X + zoff + c;

    float mx = -1e30f, s = 0.f;
    for (int r = ty; r < T_SEQ; r += 8) {
        float x = base[(long long)r * D_MODEL];
        if (x > mx) { s = s * __expf(mx - x) + 1.f; mx = x; }
        else        { s += __expf(x - mx); }
    }
    __shared__ float smx[8][32], ssm[8][32];
    smx[ty][tx] = mx; ssm[ty][tx] = s;
    __syncthreads();
    if (ty == 0) {
        float M = smx[0][tx];
#pragma unroll
        for (int k = 1; k < 8; k++) M = fmaxf(M, smx[k][tx]);
        float S = 0.f;
#pragma unroll
        for (int k = 0; k < 8; k++) S += ssm[k][tx] * __expf(smx[k][tx] - M);
        smx[0][tx] = M; ssm[0][tx] = 1.f / S;
    }
    __syncthreads();
    const float M = smx[0][tx], inv = ssm[0][tx];
    for (int r = ty; r < T_SEQ; r += 8) {
        const long long o = zoff + (long long)r * D_MODEL + c;
        P[o] = __float2half(__expf(base[(long long)r * D_MODEL] - M) * inv);
    }
}

// per-batch transpose [2048,1024] fp32 -> [1024,2048] fp16
__global__ __launch_bounds__(256)
void transpose_half_kernel(const float* __restrict__ in, __half* __restrict__ out)
{
    __shared__ float t[32][33];
    const long long zoff = (long long)blockIdx.z * T_SEQ * D_MODEL;
    const float* I = in + zoff;
    const int c0 = blockIdx.x * 32, r0 = blockIdx.y * 32;
    const int tx = threadIdx.x & 31, ty = threadIdx.x >> 5;
#pragma unroll
    for (int j = 0; j < 32; j += 8)
        t[ty + j][tx] = I[(long long)(r0 + ty + j) * D_MODEL + c0 + tx];
    __syncthreads();
#pragma unroll
    for (int j = 0; j < 32; j += 8)
        out[zoff + (long long)(c0 + ty + j) * T_SEQ + r0 + tx] = __float2half(t[tx][ty + j]);
}

// ---------------- host launcher ----------------
extern "C" void kernel_launch(void* const* d_in, const int* in_sizes, int n_in,
                              void* d_out, int out_size)
{
    const float* latent = (const float*)d_in[0];
    const float* input  = (const float*)d_in[1];
    const float* Wl = (const float*)d_in[2];
    const float* bl = (const float*)d_in[3];
    const float* Wu = (const float*)d_in[4];
    const float* bu = (const float*)d_in[5];
    const float* WA = (const float*)d_in[6];
    const float* bA = (const float*)d_in[7];
    const float* WV = (const float*)d_in[8];
    const float* bV = (const float*)d_in[9];
    const float* Wo = (const float*)d_in[10];
    const float* bo = (const float*)d_in[11];
    float* out = (float*)d_out;

    __half *lat_h, *in_h, *w_h, *p1_h, *lt_h, *ov_h, *mm_h, *pa_h;
    float* f1;
    cudaGetSymbolAddress((void**)&lat_h, g_lat_h);
    cudaGetSymbolAddress((void**)&in_h,  g_in_h);
    cudaGetSymbolAddress((void**)&w_h,   g_w_h);
    cudaGetSymbolAddress((void**)&p1_h,  g_p1_h);
    cudaGetSymbolAddress((void**)&lt_h,  g_lt_h);
    cudaGetSymbolAddress((void**)&ov_h,  g_ov_h);
    cudaGetSymbolAddress((void**)&mm_h,  g_mm_h);
    cudaGetSymbolAddress((void**)&pa_h,  g_pa_h);
    cudaGetSymbolAddress((void**)&f1,    g_f1);

    cudaFuncSetAttribute(gemm_f16,
                         cudaFuncAttributeMaxDynamicSharedMemorySize, SMEM_BYTES);

    const int D = D_MODEL;
    const int NW = D * D;
    const int NACT = MTOT * D;

    // operand prep (all single fp16 now)
    tohalf_kernel<<<NACT / 4 / 256, 256>>>((const float4*)latent, (__half2*)lat_h, NACT / 4);
    tohalf_kernel<<<NACT / 4 / 256, 256>>>((const float4*)input,  (__half2*)in_h,  NACT / 4);
    tohalf_kernel<<<NW / 4 / 256, 256>>>((const float4*)Wl, (__half2*)(w_h + 0 * NW), NW / 4);
    tohalf_kernel<<<NW / 4 / 256, 256>>>((const float4*)Wu, (__half2*)(w_h + 1 * NW), NW / 4);
    tohalf_kernel<<<NW / 4 / 256, 256>>>((const float4*)WA, (__half2*)(w_h + 2 * NW), NW / 4);
    tohalf_kernel<<<NW / 4 / 256, 256>>>((const float4*)WV, (__half2*)(w_h + 3 * NW), NW / 4);
    tohalf_kernel<<<NW / 4 / 256, 256>>>((const float4*)Wo, (__half2*)(w_h + 4 * NW), NW / 4);

    dim3 thr(256);
    dim3 gProj(D / 256, MTOT / 128, 1);       // (4, 64)

    // G1: emb0 = latent @ Wl^T + bl -> p1 (fp16)
    gemm_f16<<<gProj, thr, SMEM_BYTES>>>(lat_h, w_h + 0 * NW, bl,
                                         nullptr, p1_h, D, D, 0, 0, 0);
    // G2: s1 = emb0 @ Wu^T + bu -> f1 (fp32)
    gemm_f16<<<gProj, thr, SMEM_BYTES>>>(p1_h, w_h + 1 * NW, bu,
                                         f1, nullptr, D, D, 0, 0, 0);
    softmax_rows_1024<<<MTOT, 256>>>(f1);
    transpose_half_kernel<<<dim3(D / 32, T_SEQ / 32, NB), 256>>>(f1, lt_h);

    // G3: Dm = input @ WA^T + bA -> p1 (fp16)
    gemm_f16<<<gProj, thr, SMEM_BYTES>>>(in_h, w_h + 2 * NW, bA,
                                         nullptr, p1_h, D, D, 0, 0, 0);
    // G4: S2 = Dm @ WV^T + bV -> f1 (fp32)
    gemm_f16<<<gProj, thr, SMEM_BYTES>>>(p1_h, w_h + 3 * NW, bV,
                                         f1, nullptr, D, D, 0, 0, 0);
    softmax_cols_half<<<dim3(D / 32, NB), 256>>>(f1, pa_h);

    // G5: ov = latent @ Wo^T + bo -> f1 (fp32); transpose -> ov (fp16)
    gemm_f16<<<gProj, thr, SMEM_BYTES>>>(lat_h, w_h + 4 * NW, bo,
                                         f1, nullptr, D, D, 0, 0, 0);
    transpose_half_kernel<<<dim3(D / 32, T_SEQ / 32, NB), 256>>>(f1, ov_h);

    // G6: M^T[b] = ovT[b] @ LT[b]^T  (M=1024, N=1024, K=2048) -> mm (fp16)
    gemm_f16<<<dim3(D / 256, D / 128, NB), thr, SMEM_BYTES>>>(
        ov_h, lt_h, nullptr, nullptr, mm_h,
        D, T_SEQ, (long long)D * T_SEQ, (long long)D * T_SEQ, (long long)D * D);

    // G7: o[b] = A_sm[b] @ (M^T[b])^T  (M=2048, N=1024, K=1024) -> d_out fp32
    gemm_f16<<<dim3(D / 256, T_SEQ / 128, NB), thr, SMEM_BYTES>>>(
        pa_h, mm_h, nullptr, out, nullptr,
        D, D, (long long)T_SEQ * D, (long long)D * D, (long long)T_SEQ * D);
}

// round 6
// speedup vs baseline: 10.0510x; 1.0496x over previous
#include <cuda_runtime.h>
#include <cuda_fp16.h>
#include <cstdint>
#include <math.h>

// ITAttention on GB300, sm_103 baseline ISA. mma.sync.m16n8k16 fp16 HMMA.
// Pipeline (associativity-restructured): o = A_sm @ (L^T @ ov)
// G6 uses ldmatrix.trans on both operands so no transpose kernels are needed.

#define D_MODEL 1024
#define T_SEQ   2048
#define NB      4
#define MTOT    (NB * T_SEQ)       // 8192

// ---------------- scratch (no allocation allowed) ----------------
__device__ __align__(256) __half g_lat_h[MTOT * D_MODEL];
__device__ __align__(256) __half g_in_h [MTOT * D_MODEL];
__device__ __align__(256) __half g_w_h  [5 * D_MODEL * D_MODEL];
__device__ __align__(256) __half g_p1_h [MTOT * D_MODEL];          // emb0
__device__ __align__(256) __half g_p2_h [MTOT * D_MODEL];          // Dm
__device__ __align__(256) __half g_ls_h [MTOT * D_MODEL];          // L (row-softmaxed) [q,j]
__device__ __align__(256) __half g_ov_h [MTOT * D_MODEL];          // ov [q,e]
__device__ __align__(256) __half g_mm_h [NB * D_MODEL * D_MODEL];  // MmT [e,j]
__device__ __align__(256) __half g_pa_h [MTOT * D_MODEL];          // col-softmaxed A
__device__ __align__(256) float  g_f1  [MTOT * D_MODEL];           // fp32 staging

// ---------------- helpers ----------------
__device__ __forceinline__ uint32_t smem_u32(const void* p) {
    uint32_t a;
    asm("{ .reg .u64 t; cvta.to.shared.u64 t, %1; cvt.u32.u64 %0, t; }" : "=r"(a) : "l"(p));
    return a;
}
__device__ __forceinline__ void cp16(uint32_t dst, const void* src) {
    asm volatile("cp.async.cg.shared.global [%0], [%1], 16;" :: "r"(dst), "l"(src) : "memory");
}
__device__ __forceinline__ void cp_commit() {
    asm volatile("cp.async.commit_group;" ::: "memory");
}

#define LDSM4(r, addr)                                                            \
    asm volatile("ldmatrix.sync.aligned.m8n8.x4.shared.b16 {%0,%1,%2,%3}, [%4];"  \
                 : "=r"((r)[0]), "=r"((r)[1]), "=r"((r)[2]), "=r"((r)[3])         \
                 : "r"(addr))

#define LDSM4T(r, addr)                                                                 \
    asm volatile("ldmatrix.sync.aligned.m8n8.x4.trans.shared.b16 {%0,%1,%2,%3}, [%4];"  \
                 : "=r"((r)[0]), "=r"((r)[1]), "=r"((r)[2]), "=r"((r)[3])               \
                 : "r"(addr))

#define MMA_F16(d, a, b)                                                           \
    asm volatile("mma.sync.aligned.m16n8k16.row.col.f32.f16.f16.f32 "              \
                 "{%0,%1,%2,%3}, {%4,%5,%6,%7}, {%8,%9}, {%0,%1,%2,%3};"           \
                 : "+f"((d)[0]), "+f"((d)[1]), "+f"((d)[2]), "+f"((d)[3])          \
                 : "r"((a)[0]), "r"((a)[1]), "r"((a)[2]), "r"((a)[3]),             \
                   "r"((b)[0]), "r"((b)[1]))

// ---------------- common GEMM config ----------------
// BM=128, BN=256, BK=64. 256 threads = 8 warps (2x4), warp tile 64x64.
// smem/stage: A 16K | B 32K = 48KB; 4 stages = 192KB.
#define STG_BYTES 49152u
#define NSTAGE    4
#define SMEM_BYTES (NSTAGE * 49152)

// =======================================================================
// gemm_f16: C[M,N] = A[M,K] @ B[N,K]^T (+bias), both K-contiguous
// =======================================================================
#define LOAD_STAGE(sidx) do {                                                        \
    const uint32_t base_ = sb + (uint32_t)((sidx) & 3) * STG_BYTES;                  \
    const int k0_ = (sidx) * 64;                                                     \
    _Pragma("unroll")                                                                \
    for (int t_ = 0; t_ < 4; t_++) {                                                 \
        int idx_ = tid + 256 * t_;                                                   \
        int r_ = idx_ >> 3, c_ = idx_ & 7;                                           \
        uint32_t sm_ = base_ + (uint32_t)r_ * 128u +                                 \
                       ((uint32_t)(c_ * 16) ^ ((uint32_t)(r_ & 7) * 16u));           \
        cp16(sm_, Ah + (size_t)r_ * K + k0_ + c_ * 8);                               \
    }                                                                                \
    _Pragma("unroll")                                                                \
    for (int t_ = 0; t_ < 8; t_++) {                                                 \
        int idx_ = tid + 256 * t_;                                                   \
        int r_ = idx_ >> 3, c_ = idx_ & 7;                                           \
        uint32_t sm_ = base_ + 16384u + (uint32_t)r_ * 128u +                        \
                       ((uint32_t)(c_ * 16) ^ ((uint32_t)(r_ & 7) * 16u));           \
        cp16(sm_, Bh + (size_t)r_ * K + k0_ + c_ * 8);                               \
    }                                                                                \
    cp_commit();                                                                     \
} while (0)

__global__ void __launch_bounds__(256, 1)
gemm_f16(const __half* __restrict__ Ah, const __half* __restrict__ Bh,
         const float* __restrict__ bias,
         float* __restrict__ Cf,            // mode fp32 out
         __half* __restrict__ Ch,           // mode fp16 out
         int N, int K,
         long long aB, long long bB, long long cB)
{
    extern __shared__ char smem[];
    const uint32_t sb = smem_u32(smem);
    const int tid = threadIdx.x, lane = tid & 31, wid = tid >> 5;
    const int wm = wid >> 2, wn = wid & 3;
    const long long z = blockIdx.z;
    const int bm = blockIdx.y * 128, bn = blockIdx.x * 256;

    Ah += z * aB + (long long)bm * K;
    Bh += z * bB + (long long)bn * K;

    const int nst = K >> 6;

    LOAD_STAGE(0);
    LOAD_STAGE(1);
    LOAD_STAGE(2);

    const uint32_t swz = ((uint32_t)(lane & 7)) << 4;
    const uint32_t acsel = (uint32_t)(lane >> 4);
    uint32_t aoff[4];
#pragma unroll
    for (int i = 0; i < 4; i++)
        aoff[i] = (uint32_t)(wm * 64 + i * 16 + (lane & 15)) * 128u;
    const uint32_t bcsel = (uint32_t)((lane >> 3) & 1);
    const int brow = (lane & 7) + ((lane >> 4) << 3);
    uint32_t boff[4];
#pragma unroll
    for (int jj = 0; jj < 4; jj++)
        boff[jj] = 16384u + (uint32_t)(wn * 64 + jj * 16 + brow) * 128u;

    float acc[4][8][4];
#pragma unroll
    for (int i = 0; i < 4; i++)
#pragma unroll
        for (int j = 0; j < 8; j++)
#pragma unroll
            for (int r = 0; r < 4; r++) acc[i][j][r] = 0.f;

    for (int s = 0; s < nst; s++) {
        const int rem = nst - 1 - s;
        if (rem >= 2)      asm volatile("cp.async.wait_group 2;" ::: "memory");
        else if (rem == 1) asm volatile("cp.async.wait_group 1;" ::: "memory");
        else               asm volatile("cp.async.wait_group 0;" ::: "memory");
        __syncthreads();
        if (s + 3 < nst) LOAD_STAGE(s + 3);

        const uint32_t st = sb + (uint32_t)(s & 3) * STG_BYTES;
#pragma unroll
        for (int ks = 0; ks < 4; ks++) {
            uint32_t af[4][4];
            const uint32_t ak = (((uint32_t)(2 * ks) + acsel) << 4) ^ swz;
#pragma unroll
            for (int i = 0; i < 4; i++)
                LDSM4(af[i], st + aoff[i] + ak);
            const uint32_t bk = (((uint32_t)(2 * ks) + bcsel) << 4) ^ swz;
#pragma unroll
            for (int jj = 0; jj < 4; jj++) {
                uint32_t bf[4];
                LDSM4(bf, st + boff[jj] + bk);
#pragma unroll
                for (int i = 0; i < 4; i++) {
                    MMA_F16(acc[i][jj * 2 + 0], af[i], bf);
                    MMA_F16(acc[i][jj * 2 + 1], af[i], bf + 2);
                }
            }
        }
    }

    const int g = lane >> 2, tig = lane & 3;
    float bv[8][2];
#pragma unroll
    for (int j = 0; j < 8; j++) {
        const int n = bn + wn * 64 + j * 8 + tig * 2;
        bv[j][0] = bias ? bias[n] : 0.f;
        bv[j][1] = bias ? bias[n + 1] : 0.f;
    }
#pragma unroll
    for (int i = 0; i < 4; i++) {
        const long long m0 = bm + wm * 64 + i * 16 + g;
#pragma unroll
        for (int j = 0; j < 8; j++) {
            const int n = bn + wn * 64 + j * 8 + tig * 2;
#pragma unroll
            for (int h = 0; h < 2; h++) {
                const float v0 = acc[i][j][2 * h]     + bv[j][0];
                const float v1 = acc[i][j][2 * h + 1] + bv[j][1];
                const long long o = (z * cB) + (m0 + 8 * h) * (long long)N + n;
                if (Cf) *(float2*)(Cf + o) = make_float2(v0, v1);
                else    *(__half2*)(Ch + o) = __floats2half2_rn(v0, v1);
            }
        }
    }
}

// =======================================================================
// gemm_f16_tt: C[e,j] = sum_q A[q,e] * B[q,j]   (both stored [K=q, 1024])
// A/B row stride = D_MODEL. M=N=1024 per batch, K=Kdim. fp16 out.
// A tile [64q x 128e] (rows 256B), B tile [64q x 256j] (rows 512B),
// swizzle: 16B-unit u -> u ^ (row & 7). ldmatrix.trans for both fragments.
// =======================================================================
#define LOAD_STAGE_TT(sidx) do {                                                     \
    const uint32_t base_ = sb + (uint32_t)((sidx) & 3) * STG_BYTES;                  \
    const int k0_ = (sidx) * 64;                                                     \
    _Pragma("unroll")                                                                \
    for (int t_ = 0; t_ < 4; t_++) {                                                 \
        int idx_ = tid + 256 * t_;                                                   \
        int r_ = idx_ >> 4, u_ = idx_ & 15;                                          \
        uint32_t sm_ = base_ + (uint32_t)r_ * 256u +                                 \
                       ((uint32_t)(u_ ^ (r_ & 7)) << 4);                             \
        cp16(sm_, Ag + (size_t)(k0_ + r_) * D_MODEL + bm + u_ * 8);                  \
    }                                                                                \
    _Pragma("unroll")                                                                \
    for (int t_ = 0; t_ < 8; t_++) {                                                 \
        int idx_ = tid + 256 * t_;                                                   \
        int r_ = idx_ >> 5, u_ = idx_ & 31;                                          \
        uint32_t sm_ = base_ + 16384u + (uint32_t)r_ * 512u +                        \
                       ((uint32_t)(u_ ^ (r_ & 7)) << 4);                             \
        cp16(sm_, Bg + (size_t)(k0_ + r_) * D_MODEL + bn + u_ * 8);                  \
    }                                                                                \
    cp_commit();                                                                     \
} while (0)

__global__ void __launch_bounds__(256, 1)
gemm_f16_tt(const __half* __restrict__ A, const __half* __restrict__ B,
            __half* __restrict__ C, int Kdim,
            long long aB, long long bB, long long cB)
{
    extern __shared__ char smem[];
    const uint32_t sb = smem_u32(smem);
    const int tid = threadIdx.x, lane = tid & 31, wid = tid >> 5;
    const int wm = wid >> 2, wn = wid & 3;
    const long long z = blockIdx.z;
    const int bm = blockIdx.y * 128, bn = blockIdx.x * 256;

    const __half* Ag = A + z * aB;
    const __half* Bg = B + z * bB;

    const int nst = Kdim >> 6;

    LOAD_STAGE_TT(0);
    LOAD_STAGE_TT(1);
    LOAD_STAGE_TT(2);

    // trans-fragment addressing (derived so register contents match the
    // non-trans fragments of the transposed operands):
    //  A: row = ks*16 + ((lane>>4)<<3) + (lane&7); unit = wm*8 + 2i + ((lane>>3)&1)
    //  B: row = ks*16 + ((lane>>3)&1)*8 + (lane&7); unit = wn*8 + 2jj + (lane>>4)
    const uint32_t l7 = (uint32_t)(lane & 7);
    const int arow_k = ((lane >> 4) << 3) + (lane & 7);
    const uint32_t auadd = (uint32_t)((lane >> 3) & 1);
    const int brow_k = (((lane >> 3) & 1) << 3) + (lane & 7);
    const uint32_t buadd = (uint32_t)(lane >> 4);

    float acc[4][8][4];
#pragma unroll
    for (int i = 0; i < 4; i++)
#pragma unroll
        for (int j = 0; j < 8; j++)
#pragma unroll
            for (int r = 0; r < 4; r++) acc[i][j][r] = 0.f;

    for (int s = 0; s < nst; s++) {
        const int rem = nst - 1 - s;
        if (rem >= 2)      asm volatile("cp.async.wait_group 2;" ::: "memory");
        else if (rem == 1) asm volatile("cp.async.wait_group 1;" ::: "memory");
        else               asm volatile("cp.async.wait_group 0;" ::: "memory");
        __syncthreads();
        if (s + 3 < nst) LOAD_STAGE_TT(s + 3);

        const uint32_t st = sb + (uint32_t)(s & 3) * STG_BYTES;
#pragma unroll
        for (int ks = 0; ks < 4; ks++) {
            const uint32_t ra = (uint32_t)(ks * 16 + arow_k);
            const uint32_t rb = (uint32_t)(ks * 16 + brow_k);
            uint32_t af[4][4];
#pragma unroll
            for (int i = 0; i < 4; i++) {
                const uint32_t unit = (uint32_t)(wm * 8 + 2 * i) + auadd;
                LDSM4T(af[i], st + ra * 256u + ((unit ^ l7) << 4));
            }
#pragma unroll
            for (int jj = 0; jj < 4; jj++) {
                uint32_t bf[4];
                const uint32_t unit = (uint32_t)(wn * 8 + 2 * jj) + buadd;
                LDSM4T(bf, st + 16384u + rb * 512u + ((unit ^ l7) << 4));
#pragma unroll
                for (int i = 0; i < 4; i++) {
                    MMA_F16(acc[i][jj * 2 + 0], af[i], bf);
                    MMA_F16(acc[i][jj * 2 + 1], af[i], bf + 2);
                }
            }
        }
    }

    const int g = lane >> 2, tig = lane & 3;
#pragma unroll
    for (int i = 0; i < 4; i++) {
        const long long m0 = bm + wm * 64 + i * 16 + g;
#pragma unroll
        for (int j = 0; j < 8; j++) {
            const int n = bn + wn * 64 + j * 8 + tig * 2;
#pragma unroll
            for (int h = 0; h < 2; h++) {
                const long long o = (z * cB) + (m0 + 8 * h) * (long long)D_MODEL + n;
                *(__half2*)(C + o) = __floats2half2_rn(acc[i][j][2 * h],
                                                       acc[i][j][2 * h + 1]);
            }
        }
    }
}

// ---------------- aux kernels ----------------
__global__ __launch_bounds__(256)
void tohalf_kernel(const float4* __restrict__ in, __half2* __restrict__ out, int n4)
{
    int i = blockIdx.x * 256 + threadIdx.x;
    if (i < n4) {
        float4 v = in[i];
        out[2 * i]     = __floats2half2_rn(v.x, v.y);
        out[2 * i + 1] = __floats2half2_rn(v.z, v.w);
    }
}

// all 5 weights -> one fp16 buffer (segments of D*D). grid = 5*1024 blocks.
__global__ __launch_bounds__(256)
void tohalf5_kernel(const float4* __restrict__ w0, const float4* __restrict__ w1,
                    const float4* __restrict__ w2, const float4* __restrict__ w3,
                    const float4* __restrict__ w4, __half2* __restrict__ out)
{
    const int seg = blockIdx.x >> 10;
    const int i = ((blockIdx.x & 1023) * 256 + threadIdx.x);      // < 262144
    const float4* src = (seg == 0) ? w0 : (seg == 1) ? w1 : (seg == 2) ? w2
                       : (seg == 3) ? w3 : w4;
    float4 v = src[i];
    __half2* o = out + (size_t)seg * (D_MODEL * D_MODEL / 2) + 2 * (size_t)i;
    o[0] = __floats2half2_rn(v.x, v.y);
    o[1] = __floats2half2_rn(v.z, v.w);
}

// row softmax over 1024 columns, fp32 in -> fp16 out (same layout)
__global__ __launch_bounds__(256)
void softmax_rows_1024(const float* __restrict__ X, __half* __restrict__ O)
{
    const float* p = X + (long long)blockIdx.x * 1024;
    __half* q = O + (long long)blockIdx.x * 1024;
    const int t = threadIdx.x;
    __shared__ float red[256];
    float v[4];
#pragma unroll
    for (int j = 0; j < 4; j++) v[j] = p[t + 256 * j];
    float mx = fmaxf(fmaxf(v[0], v[1]), fmaxf(v[2], v[3]));
    red[t] = mx; __syncthreads();
    for (int s = 128; s > 0; s >>= 1) { if (t < s) red[t] = fmaxf(red[t], red[t + s]); __syncthreads(); }
    mx = red[0]; __syncthreads();
    float s = 0.f;
#pragma unroll
    for (int j = 0; j < 4; j++) { v[j] = __expf(v[j] - mx); s += v[j]; }
    red[t] = s; __syncthreads();
    for (int s2 = 128; s2 > 0; s2 >>= 1) { if (t < s2) red[t] += red[t + s2]; __syncthreads(); }
    const float inv = 1.f / red[0];
#pragma unroll
    for (int j = 0; j < 4; j++) q[t + 256 * j] = __float2half(v[j] * inv);
}

// column softmax over T_kv, fp32 in -> fp16 out. grid (1024/32, NB)
__global__ __launch_bounds__(256)
void softmax_cols_half(const float* __restrict__ X, __half* __restrict__ P)
{
    const int tx = threadIdx.x & 31;
    const int ty = threadIdx.x >> 5;
    const int c = blockIdx.x * 32 + tx;
    const long long zoff = (long long)blockIdx.y * T_SEQ * D_MODEL;
    const float* base = X + zoff + c;

    float mx = -1e30f, s = 0.f;
    for (int r = ty; r < T_SEQ; r += 8) {
        float x = base[(long long)r * D_MODEL];
        if (x > mx) { s = s * __expf(mx - x) + 1.f; mx = x; }
        else        { s += __expf(x - mx); }
    }
    __shared__ float smx[8][32], ssm[8][32];
    smx[ty][tx] = mx; ssm[ty][tx] = s;
    __syncthreads();
    if (ty == 0) {
        float M = smx[0][tx];
#pragma unroll
        for (int k = 1; k < 8; k++) M = fmaxf(M, smx[k][tx]);
        float S = 0.f;
#pragma unroll
        for (int k = 0; k < 8; k++) S += ssm[k][tx] * __expf(smx[k][tx] - M);
        smx[0][tx] = M; ssm[0][tx] = 1.f / S;
    }
    __syncthreads();
    const float M = smx[0][tx], inv = ssm[0][tx];
    for (int r = ty; r < T_SEQ; r += 8) {
        const long long o = zoff + (long long)r * D_MODEL + c;
        P[o] = __float2half(__expf(base[(long long)r * D_MODEL] - M) * inv);
    }
}

// ---------------- host launcher ----------------
extern "C" void kernel_launch(void* const* d_in, const int* in_sizes, int n_in,
                              void* d_out, int out_size)
{
    const float* latent = (const float*)d_in[0];
    const float* input  = (const float*)d_in[1];
    const float* Wl = (const float*)d_in[2];
    const float* bl = (const float*)d_in[3];
    const float* Wu = (const float*)d_in[4];
    const float* bu = (const float*)d_in[5];
    const float* WA = (const float*)d_in[6];
    const float* bA = (const float*)d_in[7];
    const float* WV = (const float*)d_in[8];
    const float* bV = (const float*)d_in[9];
    const float* Wo = (const float*)d_in[10];
    const float* bo = (const float*)d_in[11];
    float* out = (float*)d_out;

    __half *lat_h, *in_h, *w_h, *p1_h, *p2_h, *ls_h, *ov_h, *mm_h, *pa_h;
    float* f1;
    cudaGetSymbolAddress((void**)&lat_h, g_lat_h);
    cudaGetSymbolAddress((void**)&in_h,  g_in_h);
    cudaGetSymbolAddress((void**)&w_h,   g_w_h);
    cudaGetSymbolAddress((void**)&p1_h,  g_p1_h);
    cudaGetSymbolAddress((void**)&p2_h,  g_p2_h);
    cudaGetSymbolAddress((void**)&ls_h,  g_ls_h);
    cudaGetSymbolAddress((void**)&ov_h,  g_ov_h);
    cudaGetSymbolAddress((void**)&mm_h,  g_mm_h);
    cudaGetSymbolAddress((void**)&pa_h,  g_pa_h);
    cudaGetSymbolAddress((void**)&f1,    g_f1);

    cudaFuncSetAttribute(gemm_f16,
                         cudaFuncAttributeMaxDynamicSharedMemorySize, SMEM_BYTES);
    cudaFuncSetAttribute(gemm_f16_tt,
                         cudaFuncAttributeMaxDynamicSharedMemorySize, SMEM_BYTES);

    const int D = D_MODEL;
    const int NW = D * D;
    const int NACT = MTOT * D;

    // 1-3: operand prep (3 launches so ncu -s 5 catches launch #6 = G2)
    tohalf_kernel<<<NACT / 4 / 256, 256>>>((const float4*)latent, (__half2*)lat_h, NACT / 4);
    tohalf_kernel<<<NACT / 4 / 256, 256>>>((const float4*)input,  (__half2*)in_h,  NACT / 4);
    tohalf5_kernel<<<5 * (NW / 4 / 256), 256>>>((const float4*)Wl, (const float4*)Wu,
                                                (const float4*)WA, (const float4*)WV,
                                                (const float4*)Wo, (__half2*)w_h);

    dim3 thr(256);
    dim3 gProj(D / 256, MTOT / 128, 1);       // (4, 64)

    // 4: G1: emb0 = latent @ Wl^T + bl -> p1 (fp16)
    gemm_f16<<<gProj, thr, SMEM_BYTES>>>(lat_h, w_h + 0 * NW, bl,
                                         nullptr, p1_h, D, D, 0, 0, 0);
    // 5: G3: Dm = input @ WA^T + bA -> p2 (fp16)
    gemm_f16<<<gProj, thr, SMEM_BYTES>>>(in_h, w_h + 2 * NW, bA,
                                         nullptr, p2_h, D, D, 0, 0, 0);
    // 6: G2: s1 = emb0 @ Wu^T + bu -> f1 (fp32)   [ncu profiles this launch]
    gemm_f16<<<gProj, thr, SMEM_BYTES>>>(p1_h, w_h + 1 * NW, bu,
                                         f1, nullptr, D, D, 0, 0, 0);
    // 7: row softmax -> L fp16 [q,j]
    softmax_rows_1024<<<MTOT, 256>>>(f1, ls_h);
    // 8: G5: ov = latent @ Wo^T + bo -> ov fp16 [q,e]
    gemm_f16<<<gProj, thr, SMEM_BYTES>>>(lat_h, w_h + 4 * NW, bo,
                                         nullptr, ov_h, D, D, 0, 0, 0);
    // 9: G4: S2 = Dm @ WV^T + bV -> f1 (fp32)
    gemm_f16<<<gProj, thr, SMEM_BYTES>>>(p2_h, w_h + 3 * NW, bV,
                                         f1, nullptr, D, D, 0, 0, 0);
    // 10: col softmax over T_kv -> pa fp16
    softmax_cols_half<<<dim3(D / 32, NB), 256>>>(f1, pa_h);

    // 11: G6 (trans-trans): MmT[e,j] = sum_q ov[q,e] * L[q,j]  -> mm fp16
    gemm_f16_tt<<<dim3(D / 256, D / 128, NB), thr, SMEM_BYTES>>>(
        ov_h, ls_h, mm_h, T_SEQ,
        (long long)T_SEQ * D, (long long)T_SEQ * D, (long long)D * D);

    // 12: G7: o[b] = pa @ MmT^T  (M=2048, N=1024, K=1024) -> d_out fp32
    gemm_f16<<<dim3(D / 256, T_SEQ / 128, NB), thr, SMEM_BYTES>>>(
        pa_h, mm_h, nullptr, out, nullptr,
        D, D, (long long)T_SEQ * D, (long long)D * D, (long long)T_SEQ * D);
}